// round 11
// baseline (speedup 1.0000x reference)
#include <cuda_runtime.h>
#include <cuda_fp16.h>
#include <cuda_bf16.h>
#include <cstdint>

// ---------------------------------------------------------------------------
// Problem constants
// ---------------------------------------------------------------------------
#define BATCH   4
#define SEQ     4096
#define DMODEL  1024
#define NHEADS  8
#define HDIM    64
#define STATE   512            // NHEADS*HDIM
#define PROJW   2048           // 4*STATE
#define ROWS    (BATCH*SEQ)    // 16384

// GEMM tiling: block 128x256, 8 warps of 64x64, fp16 HMMA m16n8k16
#define BM 128
#define BN 256
#define NSTAGE 5
#define ROWB 48                         // padded smem row stride (bytes)
#define A_STAGE_B (BM * ROWB)           // 6144 B
#define B_STAGE_B (BN * ROWB)           // 12288 B
#define SMEM_DYN_BYTES (NSTAGE * (A_STAGE_B + B_STAGE_B))   // 92160 B

// ---------------------------------------------------------------------------
// Scratch (device globals -- no runtime allocation allowed)
// ---------------------------------------------------------------------------
__device__ float  g_proj[(size_t)ROWS * PROJW];   // [xi_raw | xf | xr | g]
__device__ float  g_xi  [(size_t)ROWS * STATE];   // conv+silu output
__device__ float  g_y   [(size_t)ROWS * STATE];   // recurrence output
__device__ __half g_xh  [(size_t)ROWS * DMODEL];  // x (fp16)
__device__ __half g_winh[(size_t)PROJW * DMODEL]; // w_in (fp16)
__device__ __half g_wouth[(size_t)DMODEL * STATE];// w_out (fp16)
__device__ __half g_ynh [(size_t)ROWS * STATE];   // gated+normed (fp16)

// ---------------------------------------------------------------------------
// Helpers (scan)
// ---------------------------------------------------------------------------
__device__ __forceinline__ unsigned long long pk2(float lo, float hi) {
    unsigned long long r;
    asm("mov.b64 %0, {%1, %2};" : "=l"(r) : "f"(lo), "f"(hi));
    return r;
}
__device__ __forceinline__ void fma2(unsigned long long& d,
                                     unsigned long long a,
                                     unsigned long long b) {
    asm("fma.rn.f32x2 %0, %1, %2, %0;" : "+l"(d) : "l"(a), "l"(b));
}
__device__ __forceinline__ unsigned long long add2(unsigned long long a,
                                                   unsigned long long b) {
    unsigned long long d;
    asm("add.rn.f32x2 %0, %1, %2;" : "=l"(d) : "l"(a), "l"(b));
    return d;
}
__device__ __forceinline__ float hadd2(unsigned long long v) {
    float a, b;
    asm("mov.b64 {%0, %1}, %2;" : "=f"(a), "=f"(b) : "l"(v));
    return a + b;
}
__device__ __forceinline__ float fsigmoid(float x) {
    return __fdividef(1.0f, 1.0f + __expf(-x));
}
// HW tanh approximation (sm_75+): single MUFU-class op, max rel err ~2^-11
__device__ __forceinline__ float tanh_fast(float x) {
    float y;
    asm("tanh.approx.f32 %0, %1;" : "=f"(y) : "f"(x));
    return y;
}
// sigmoid via tanh.approx: sigma(x) = 0.5 + 0.5*tanh(x/2)
__device__ __forceinline__ float sigmoid_fast(float x) {
    return fmaf(0.5f, tanh_fast(0.5f * x), 0.5f);
}

// ---------------------------------------------------------------------------
// GEMM primitives
// ---------------------------------------------------------------------------
__device__ __forceinline__ void mma_f16(float* c, const uint32_t* a,
                                        uint32_t b0, uint32_t b1) {
    asm volatile(
        "mma.sync.aligned.m16n8k16.row.col.f32.f16.f16.f32 "
        "{%0,%1,%2,%3}, {%4,%5,%6,%7}, {%8,%9}, {%0,%1,%2,%3};\n"
        : "+f"(c[0]), "+f"(c[1]), "+f"(c[2]), "+f"(c[3])
        : "r"(a[0]), "r"(a[1]), "r"(a[2]), "r"(a[3]), "r"(b0), "r"(b1));
}
__device__ __forceinline__ void ldsm4(uint32_t& r0, uint32_t& r1,
                                      uint32_t& r2, uint32_t& r3,
                                      uint32_t addr) {
    asm volatile("ldmatrix.sync.aligned.m8n8.x4.shared.b16 "
                 "{%0,%1,%2,%3}, [%4];"
                 : "=r"(r0), "=r"(r1), "=r"(r2), "=r"(r3) : "r"(addr));
}
__device__ __forceinline__ void cp16(uint32_t dst, const void* src) {
    asm volatile("cp.async.cg.shared.global [%0], [%1], 16;\n"
                 :: "r"(dst), "l"(src));
}

// ---------------------------------------------------------------------------
// Pre-pass: fp32 -> fp16 (rn), 8 elems/thread
// ---------------------------------------------------------------------------
__global__ void __launch_bounds__(256)
f32_to_f16_kernel(const float* __restrict__ src, __half* __restrict__ dst,
                  int n8)
{
    int g = blockIdx.x * 256 + threadIdx.x;
    if (g >= n8) return;
    const float4* s = (const float4*)(src + (size_t)g * 8);
    float4 a = s[0], b = s[1];
    __half2 h0 = __floats2half2_rn(a.x, a.y);
    __half2 h1 = __floats2half2_rn(a.z, a.w);
    __half2 h2 = __floats2half2_rn(b.x, b.y);
    __half2 h3 = __floats2half2_rn(b.z, b.w);
    uint4 o;
    o.x = *(uint32_t*)&h0; o.y = *(uint32_t*)&h1;
    o.z = *(uint32_t*)&h2; o.w = *(uint32_t*)&h3;
    *(uint4*)(dst + (size_t)g * 8) = o;
}

// ---------------------------------------------------------------------------
// 128x256 fp16 GEMM body (NT): C[m,n] = sum_k A[m,k]*B[n,k], fp32 accum/out.
// 256 threads, 8 warps of 64x64, cp.async 5-stage, ldmatrix fragments.
// ---------------------------------------------------------------------------
__device__ __forceinline__ void gemm_body(const __half* __restrict__ Ag0,
                                          const __half* __restrict__ Bg0,
                                          float* __restrict__ Cg0,
                                          int K, int ldc)
{
    extern __shared__ char smem_dyn[];
    char* Asm = smem_dyn;
    char* Bsm = smem_dyn + NSTAGE * A_STAGE_B;
    const uint32_t aBase = (uint32_t)__cvta_generic_to_shared(Asm);
    const uint32_t bBase = (uint32_t)__cvta_generic_to_shared(Bsm);

    const int tid   = threadIdx.x;
    const int lane  = tid & 31;
    const int warp  = tid >> 5;
    const int group = lane >> 2;
    const int tig   = lane & 3;
    const int wm = (warp >> 2) * 64;   // 2 warp rows
    const int wn = (warp & 3) * 64;    // 4 warp cols

    const int lj = lane >> 3;          // ldmatrix matrix id 0..3
    const int lrr = lane & 7;
    const uint32_t fragOff =
        (uint32_t)(((lj & 1) * 8 + lrr) * ROWB + (lj >> 1) * 16);

    float c[4][8][4];
#pragma unroll
    for (int mt = 0; mt < 4; mt++)
#pragma unroll
        for (int nt = 0; nt < 8; nt++)
#pragma unroll
            for (int q = 0; q < 4; q++) c[mt][nt][q] = 0.0f;

    const int arow  = tid >> 1;
    const int ahalf = tid & 1;
    const uint32_t aOff  = (uint32_t)(arow * ROWB + ahalf * 16);
    const uint32_t bOff0 = aOff;
    const uint32_t bOff1 = (uint32_t)((arow + 128) * ROWB + ahalf * 16);
    const int niter = K >> 4;

    auto load_stage = [&](int st, int ko) {
        const uint32_t aS = aBase + (uint32_t)(st * A_STAGE_B);
        const uint32_t bS = bBase + (uint32_t)(st * B_STAGE_B);
        cp16(aS + aOff,  Ag0 + (size_t)arow * K + ko + ahalf * 8);
        cp16(bS + bOff0, Bg0 + (size_t)arow * K + ko + ahalf * 8);
        cp16(bS + bOff1, Bg0 + (size_t)(arow + 128) * K + ko + ahalf * 8);
        asm volatile("cp.async.commit_group;\n");
    };

    load_stage(0, 0);
    load_stage(1, 16);
    load_stage(2, 32);
    load_stage(3, 48);

    int st = 0, ldst = 4;
    for (int it = 0; it < niter; it++) {
        asm volatile("cp.async.wait_group 3;\n");
        __syncthreads();

        const uint32_t aT = aBase + (uint32_t)(st * A_STAGE_B);
        const uint32_t bT = bBase + (uint32_t)(st * B_STAGE_B);

        uint32_t a[4][4], bf[4][4];
#pragma unroll
        for (int mt = 0; mt < 4; mt++)
            ldsm4(a[mt][0], a[mt][1], a[mt][2], a[mt][3],
                  aT + (uint32_t)((wm + mt * 16) * ROWB) + fragOff);
#pragma unroll
        for (int bt = 0; bt < 4; bt++)
            ldsm4(bf[bt][0], bf[bt][1], bf[bt][2], bf[bt][3],
                  bT + (uint32_t)((wn + bt * 16) * ROWB) + fragOff);

#pragma unroll
        for (int mt = 0; mt < 4; mt++)
#pragma unroll
            for (int nt = 0; nt < 8; nt++) {
                const int bt = nt >> 1, s = nt & 1;
                mma_f16(c[mt][nt], a[mt], bf[bt][s], bf[bt][s + 2]);
            }

        if (it + 4 < niter)
            load_stage(ldst, (it + 4) * 16);
        else
            asm volatile("cp.async.commit_group;\n");

        st   = (st   + 1 == NSTAGE) ? 0 : st + 1;
        ldst = (ldst + 1 == NSTAGE) ? 0 : ldst + 1;
    }

#pragma unroll
    for (int mt = 0; mt < 4; mt++) {
        const int m0 = wm + mt * 16 + group;
#pragma unroll
        for (int nt = 0; nt < 8; nt++) {
            const int n0 = wn + nt * 8 + 2 * tig;
            *(float2*)(Cg0 + (size_t)m0 * ldc + n0) =
                make_float2(c[mt][nt][0], c[mt][nt][1]);
            *(float2*)(Cg0 + (size_t)(m0 + 8) * ldc + n0) =
                make_float2(c[mt][nt][2], c[mt][nt][3]);
        }
    }
}

__global__ void __launch_bounds__(256)
f16_gemm_nt(const __half* __restrict__ A, const __half* __restrict__ B,
            float* __restrict__ C, int K, int ldc)
{
    gemm_body(A + (size_t)blockIdx.y * BM * K,
              B + (size_t)blockIdx.x * BN * K,
              C + (size_t)blockIdx.y * BM * ldc + blockIdx.x * BN,
              K, ldc);
}

// ---------------------------------------------------------------------------
// Sequential recurrence: 256 threads, one (b,head) per block.
// Gate dots: 2 threads/output (halves), shfl_xor(16) combine — same warp.
//   warps 0-3 = f outputs 0..63, warps 4-7 = r outputs 0..63.
// z dot: 4 threads/output (quarters), shfl_xor(8)+shfl_xor(16) combine.
// 2 __syncthreads per step. f-gate passed to z-updater via gate_sh.
// ---------------------------------------------------------------------------
__device__ void scan_body(const float* __restrict__ proj,
                          const float* __restrict__ xi_in,
                          const float* __restrict__ sw,
                          float* __restrict__ y, int bh)
{
    const int tid  = threadIdx.x;
    const int w    = tid >> 5;
    const int l    = tid & 31;
    const bool isr = (w >= 4);
    const int go   = (w & 3) * 16 + (l & 15);   // gate output 0..63
    const int q    = l >> 4;                    // summation half 0/1
    const int zo   = ((w & 7) << 3) | (l & 7);  // z output 0..63
    const int p    = l >> 3;                    // summation quarter 0..3
    const int head = bh & 7;
    const int b    = bh >> 3;

    __shared__ __align__(16) float h_sh[64];
    __shared__ __align__(16) float hr_sh[64];
    __shared__ __align__(16) float gate_sh[64];

    // wg: half-column go of Wf (warps 0-3) / Wr (warps 4-7), rows [32q,32q+32)
    unsigned long long wg[16];
    {
        const int gidx = isr ? (2 * NHEADS + head) : (NHEADS + head);
        const float* base = sw + (size_t)gidx * 4096 + go;
#pragma unroll
        for (int i = 0; i < 16; i++)
            wg[i] = pk2(base[(32 * q + 2 * i) * 64],
                        base[(32 * q + 2 * i + 1) * 64]);
    }
    // wz: quarter-column zo of W, rows [16p, 16p+16)
    unsigned long long wz[8];
    {
        const float* bz = sw + (size_t)head * 4096 + zo;
#pragma unroll
        for (int i = 0; i < 8; i++)
            wz[i] = pk2(bz[(16 * p + 2 * i) * 64],
                        bz[(16 * p + 2 * i + 1) * 64]);
    }

    if (tid < 64) h_sh[tid] = 0.0f;
    __syncthreads();

    const float* xg_ptr = proj + (size_t)b * SEQ * PROJW
                          + (isr ? 2 * STATE : STATE) + head * HDIM + go;
    const float* xi_ptr = xi_in + (size_t)b * SEQ * STATE + head * HDIM + zo;
    float* y_ptr = y + (size_t)b * SEQ * STATE + head * HDIM + zo;

    // 8-deep prefetch (per-thread)
    float xg_buf[8], xi_buf[8];
#pragma unroll
    for (int j = 0; j < 8; j++) {
        xg_buf[j] = xg_ptr[(size_t)j * PROJW];
        xi_buf[j] = xi_ptr[(size_t)j * STATE];
    }

    const ulonglong2* hp  = (const ulonglong2*)h_sh  + q * 8;
    const ulonglong2* hrp = (const ulonglong2*)hr_sh + p * 4;

    for (int t0 = 0; t0 < SEQ; t0 += 8) {
#pragma unroll
        for (int j = 0; j < 8; j++) {
            const int t = t0 + j;
            const float xg  = xg_buf[j];
            const float xiv = xi_buf[j];
            int tp = t + 8; if (tp > SEQ - 1) tp = SEQ - 1;
            xg_buf[j] = xg_ptr[(size_t)tp * PROJW];
            xi_buf[j] = xi_ptr[(size_t)tp * STATE];

            // ---- phase A: half gate dot (16 fma2) + shfl combine ----
            unsigned long long a0 = 0ull, a1 = 0ull, a2 = 0ull, a3 = 0ull;
#pragma unroll
            for (int i = 0; i < 4; i++) {
                ulonglong2 p0 = hp[2 * i];
                ulonglong2 p1 = hp[2 * i + 1];
                fma2(a0, p0.x, wg[4 * i + 0]);
                fma2(a1, p0.y, wg[4 * i + 1]);
                fma2(a2, p1.x, wg[4 * i + 2]);
                fma2(a3, p1.y, wg[4 * i + 3]);
            }
            float part = hadd2(add2(add2(a0, a1), add2(a2, a3)));
            part += __shfl_xor_sync(0xffffffffu, part, 16);
            const float gate = sigmoid_fast(part + xg);
            if (q == 0) {
                if (isr) hr_sh[go] = h_sh[go] * gate;   // h*r
                else     gate_sh[go] = gate;            // f gate
            }
            __syncthreads();                            // 1: hr + gate visible

            // ---- phase B: quarter z dot (8 fma2) + 2 shfl combine ----
            unsigned long long z0 = 0ull, z1 = 0ull, z2 = 0ull, z3 = 0ull;
#pragma unroll
            for (int i = 0; i < 2; i++) {
                ulonglong2 p0 = hrp[2 * i];
                ulonglong2 p1 = hrp[2 * i + 1];
                fma2(z0, p0.x, wz[4 * i + 0]);
                fma2(z1, p0.y, wz[4 * i + 1]);
                fma2(z2, p1.x, wz[4 * i + 2]);
                fma2(z3, p1.y, wz[4 * i + 3]);
            }
            float zp = hadd2(add2(add2(z0, z1), add2(z2, z3)));
            zp += __shfl_xor_sync(0xffffffffu, zp, 8);
            zp += __shfl_xor_sync(0xffffffffu, zp, 16);
            if (p == 0) {                               // one thread per zo
                const float z  = tanh_fast(zp + xiv);
                const float hk = h_sh[zo];
                const float f  = gate_sh[zo];
                const float hn = fmaf(f, hk - z, z);    // f*h + (1-f)*z
                h_sh[zo] = hn;
                y_ptr[(size_t)t * STATE] = hn;
            }
            __syncthreads();                            // 2: new h visible
        }
    }
}

// ---------------------------------------------------------------------------
// Fused: blocks 0..31 -> scan (256 thr); blocks 32.. -> g-column GEMM
// ---------------------------------------------------------------------------
__global__ void __launch_bounds__(256)
fused_scan_ggemm(const float* __restrict__ proj_in,
                 const float* __restrict__ xi_in,
                 const float* __restrict__ sw,
                 float* __restrict__ y,
                 const __half* __restrict__ xh,
                 const __half* __restrict__ winh,
                 float* __restrict__ proj_out)
{
    if (blockIdx.x < 32) {
        scan_body(proj_in, xi_in, sw, y, blockIdx.x);
    } else {
        const int idx = blockIdx.x - 32;
        const int bx = idx & 1;        // 2 n-tiles (512 cols)
        const int by = idx >> 1;       // 128 m-tiles
        gemm_body(xh + (size_t)by * BM * DMODEL,
                  winh + (size_t)(3 * STATE + bx * BN) * DMODEL,
                  proj_out + (size_t)by * BM * PROJW + 3 * STATE + bx * BN,
                  DMODEL, PROJW);
    }
}

// ---------------------------------------------------------------------------
// Depthwise causal conv (K=4) over xi (= proj[:, :512]) + SiLU -> g_xi
// ---------------------------------------------------------------------------
__global__ void conv_silu_kernel(const float* __restrict__ proj,
                                 const float* __restrict__ cw,
                                 float* __restrict__ xi)
{
    int idx = blockIdx.x * 256 + threadIdx.x;           // over ROWS*STATE
    if (idx >= ROWS * STATE) return;
    int c   = idx & (STATE - 1);
    int row = idx >> 9;
    int s   = row & (SEQ - 1);
    float acc = 0.0f;
#pragma unroll
    for (int kk = 0; kk < 4; kk++) {
        int d = kk - 3;
        if (s + d >= 0)
            acc += cw[c * 4 + kk] * proj[(size_t)(row + d) * PROJW + c];
    }
    xi[idx] = acc * fsigmoid(acc);
}

// ---------------------------------------------------------------------------
// Epilogue: v = y * silu(g); rmsnorm; * norm_w; -> fp16 yn (GEMM2's A)
// ---------------------------------------------------------------------------
__global__ void __launch_bounds__(128)
epilogue_kernel(const float* __restrict__ y, const float* __restrict__ proj,
                const float* __restrict__ norm_w, __half* __restrict__ yn)
{
    const int row = blockIdx.x;
    const int tid = threadIdx.x;
    const float* yr = y    + (size_t)row * STATE;
    const float* gr = proj + (size_t)row * PROJW + 3 * STATE;

    float v[4];
    float ss = 0.0f;
#pragma unroll
    for (int q = 0; q < 4; q++) {
        int c = tid + q * 128;
        float g = gr[c];
        float val = yr[c] * g * fsigmoid(g);
        v[q] = val;
        ss += val * val;
    }
#pragma unroll
    for (int off = 16; off > 0; off >>= 1)
        ss += __shfl_xor_sync(0xffffffffu, ss, off);
    __shared__ float red[4];
    if ((tid & 31) == 0) red[tid >> 5] = ss;
    __syncthreads();
    float tot = red[0] + red[1] + red[2] + red[3];
    float scale = rsqrtf(tot * (1.0f / 512.0f) + 1e-6f);
#pragma unroll
    for (int q = 0; q < 4; q++) {
        int c = tid + q * 128;
        yn[(size_t)row * STATE + c] = __float2half_rn(v[q] * scale * norm_w[c]);
    }
}

// ---------------------------------------------------------------------------
// Launch
// ---------------------------------------------------------------------------
extern "C" void kernel_launch(void* const* d_in, const int* in_sizes, int n_in,
                              void* d_out, int out_size)
{
    const float* x      = (const float*)d_in[0];
    const float* w_in   = (const float*)d_in[1];
    const float* conv_w = (const float*)d_in[2];
    const float* sw     = (const float*)d_in[3];
    const float* norm_w = (const float*)d_in[4];
    const float* w_out  = (const float*)d_in[5];
    float* out = (float*)d_out;

    float *proj, *xi, *y;
    __half *xh, *winh, *wouth, *ynh;
    cudaGetSymbolAddress((void**)&proj,  g_proj);
    cudaGetSymbolAddress((void**)&xi,    g_xi);
    cudaGetSymbolAddress((void**)&y,     g_y);
    cudaGetSymbolAddress((void**)&xh,    g_xh);
    cudaGetSymbolAddress((void**)&winh,  g_winh);
    cudaGetSymbolAddress((void**)&wouth, g_wouth);
    cudaGetSymbolAddress((void**)&ynh,   g_ynh);

    cudaFuncSetAttribute(f16_gemm_nt,
                         cudaFuncAttributeMaxDynamicSharedMemorySize,
                         SMEM_DYN_BYTES);
    cudaFuncSetAttribute(fused_scan_ggemm,
                         cudaFuncAttributeMaxDynamicSharedMemorySize,
                         SMEM_DYN_BYTES);

    // 0. fp32 -> fp16 conversions
    f32_to_f16_kernel<<<(ROWS * DMODEL / 8 + 255) / 256, 256>>>(
        x, xh, ROWS * DMODEL / 8);
    f32_to_f16_kernel<<<(PROJW * DMODEL / 8 + 255) / 256, 256>>>(
        w_in, winh, PROJW * DMODEL / 8);
    f32_to_f16_kernel<<<(DMODEL * STATE / 8 + 255) / 256, 256>>>(
        w_out, wouth, DMODEL * STATE / 8);

    // 1. proj[:, 0:1536] = x @ w_in[0:1536]^T  (xi_raw | xf | xr)
    {
        dim3 grid(6, ROWS / BM);   // 6 n-tiles of 256 = 1536 cols
        f16_gemm_nt<<<grid, 256, SMEM_DYN_BYTES>>>(xh, winh, proj,
                                                   DMODEL, PROJW);
    }
    // 2. depthwise conv + silu -> xi  (also warms L2 for the scan)
    conv_silu_kernel<<<(ROWS * STATE) / 256, 256>>>(proj, conv_w, xi);
    // 3. fused: sequential recurrence (32 blocks) + g-column GEMM (256 blocks)
    fused_scan_ggemm<<<32 + 2 * (ROWS / BM), 256, SMEM_DYN_BYTES>>>(
        proj, xi, sw, y, xh, winh, proj);
    // 4. gate + rmsnorm -> ynh (fp16)
    epilogue_kernel<<<ROWS, 128>>>(y, proj, norm_w, ynh);
    // 5. out = yn @ w_out^T  (16384 x 1024 x 512)
    {
        dim3 grid(DMODEL / BN, ROWS / BM);  // 4 x 128
        f16_gemm_nt<<<grid, 256, SMEM_DYN_BYTES>>>(ynh, wouth, out,
                                                   STATE, DMODEL);
    }
}

// round 12
// speedup vs baseline: 1.2946x; 1.2946x over previous
#include <cuda_runtime.h>
#include <cuda_fp16.h>
#include <cuda_bf16.h>
#include <cstdint>

// ---------------------------------------------------------------------------
// Problem constants
// ---------------------------------------------------------------------------
#define BATCH   4
#define SEQ     4096
#define DMODEL  1024
#define NHEADS  8
#define HDIM    64
#define STATE   512            // NHEADS*HDIM
#define PROJW   2048           // 4*STATE
#define ROWS    (BATCH*SEQ)    // 16384

// GEMM tiling: block 128x256, 8 warps of 64x64, fp16 HMMA m16n8k16
#define BM 128
#define BN 256
#define NSTAGE 5
#define ROWB 48                         // padded smem row stride (bytes)
#define A_STAGE_B (BM * ROWB)           // 6144 B
#define B_STAGE_B (BN * ROWB)           // 12288 B
#define GEMM_SMEM_BYTES (NSTAGE * (A_STAGE_B + B_STAGE_B))   // 92160 B

#define NTILES_N 8                      // 2048 / BN
#define NMTILES  128                    // ROWS / BM

// Scan input staging: chunks of 64 steps, 3 operands (xi_raw | xf | xr)
#define CHUNK    64
#define NCHUNKS  (SEQ / CHUNK)          // 64
#define OP_STRIDE  (CHUNK * 64)         // 4096 floats per operand
#define BUF_STRIDE (3 * OP_STRIDE)      // 12288 floats per buffer
#define SCAN_SMEM_BYTES (2 * BUF_STRIDE * 4)   // 98304 B

#define SMEM_DYN_BYTES (SCAN_SMEM_BYTES > GEMM_SMEM_BYTES ? \
                        SCAN_SMEM_BYTES : GEMM_SMEM_BYTES)   // 98304

// ---------------------------------------------------------------------------
// Scratch (device globals -- no runtime allocation allowed)
// ---------------------------------------------------------------------------
__device__ float  g_proj[(size_t)ROWS * PROJW];   // [xi_raw | xf | xr | g]
__device__ float  g_y   [(size_t)ROWS * STATE];   // recurrence output
__device__ __half g_xh  [(size_t)ROWS * DMODEL];  // x (fp16)
__device__ __half g_winh[(size_t)PROJW * DMODEL]; // w_in (fp16)
__device__ __half g_wouth[(size_t)DMODEL * STATE];// w_out (fp16)
__device__ __half g_ynh [(size_t)ROWS * STATE];   // gated+normed (fp16)
__device__ int    g_flags[NMTILES];               // per m-tile completion (8=done)

// ---------------------------------------------------------------------------
// Helpers (scan)
// ---------------------------------------------------------------------------
__device__ __forceinline__ unsigned long long pk2(float lo, float hi) {
    unsigned long long r;
    asm("mov.b64 %0, {%1, %2};" : "=l"(r) : "f"(lo), "f"(hi));
    return r;
}
__device__ __forceinline__ void fma2(unsigned long long& d,
                                     unsigned long long a,
                                     unsigned long long b) {
    asm("fma.rn.f32x2 %0, %1, %2, %0;" : "+l"(d) : "l"(a), "l"(b));
}
__device__ __forceinline__ unsigned long long add2(unsigned long long a,
                                                   unsigned long long b) {
    unsigned long long d;
    asm("add.rn.f32x2 %0, %1, %2;" : "=l"(d) : "l"(a), "l"(b));
    return d;
}
__device__ __forceinline__ float hadd2(unsigned long long v) {
    float a, b;
    asm("mov.b64 {%0, %1}, %2;" : "=f"(a), "=f"(b) : "l"(v));
    return a + b;
}
__device__ __forceinline__ float fsigmoid(float x) {
    return __fdividef(1.0f, 1.0f + __expf(-x));
}
__device__ __forceinline__ float tanh_fast(float x) {
    float y;
    asm("tanh.approx.f32 %0, %1;" : "=f"(y) : "f"(x));
    return y;
}
__device__ __forceinline__ float sigmoid_fast(float x) {
    return fmaf(0.5f, tanh_fast(0.5f * x), 0.5f);
}
__device__ __forceinline__ int ld_acq(const int* p) {
    int v;
    asm volatile("ld.global.acquire.gpu.b32 %0, [%1];" : "=r"(v) : "l"(p));
    return v;
}
__device__ __forceinline__ void wait_flag(const int* p) {
    while (ld_acq(p) < NTILES_N) { __nanosleep(64); }
}

// ---------------------------------------------------------------------------
// GEMM primitives
// ---------------------------------------------------------------------------
__device__ __forceinline__ void mma_f16(float* c, const uint32_t* a,
                                        uint32_t b0, uint32_t b1) {
    asm volatile(
        "mma.sync.aligned.m16n8k16.row.col.f32.f16.f16.f32 "
        "{%0,%1,%2,%3}, {%4,%5,%6,%7}, {%8,%9}, {%0,%1,%2,%3};\n"
        : "+f"(c[0]), "+f"(c[1]), "+f"(c[2]), "+f"(c[3])
        : "r"(a[0]), "r"(a[1]), "r"(a[2]), "r"(a[3]), "r"(b0), "r"(b1));
}
__device__ __forceinline__ void ldsm4(uint32_t& r0, uint32_t& r1,
                                      uint32_t& r2, uint32_t& r3,
                                      uint32_t addr) {
    asm volatile("ldmatrix.sync.aligned.m8n8.x4.shared.b16 "
                 "{%0,%1,%2,%3}, [%4];"
                 : "=r"(r0), "=r"(r1), "=r"(r2), "=r"(r3) : "r"(addr));
}
__device__ __forceinline__ void cp16(uint32_t dst, const void* src) {
    asm volatile("cp.async.cg.shared.global [%0], [%1], 16;\n"
                 :: "r"(dst), "l"(src));
}

// ---------------------------------------------------------------------------
// Flag reset (graph-replay safe)
// ---------------------------------------------------------------------------
__global__ void zero_flags_kernel() { g_flags[threadIdx.x] = 0; }

// ---------------------------------------------------------------------------
// Pre-pass: fp32 -> fp16 (rn), 8 elems/thread
// ---------------------------------------------------------------------------
__global__ void __launch_bounds__(256)
f32_to_f16_kernel(const float* __restrict__ src, __half* __restrict__ dst,
                  int n8)
{
    int g = blockIdx.x * 256 + threadIdx.x;
    if (g >= n8) return;
    const float4* s = (const float4*)(src + (size_t)g * 8);
    float4 a = s[0], b = s[1];
    __half2 h0 = __floats2half2_rn(a.x, a.y);
    __half2 h1 = __floats2half2_rn(a.z, a.w);
    __half2 h2 = __floats2half2_rn(b.x, b.y);
    __half2 h3 = __floats2half2_rn(b.z, b.w);
    uint4 o;
    o.x = *(uint32_t*)&h0; o.y = *(uint32_t*)&h1;
    o.z = *(uint32_t*)&h2; o.w = *(uint32_t*)&h3;
    *(uint4*)(dst + (size_t)g * 8) = o;
}

// ---------------------------------------------------------------------------
// 128x256 fp16 GEMM body (NT): C[m,n] = sum_k A[m,k]*B[n,k], fp32 accum/out.
// ---------------------------------------------------------------------------
__device__ __forceinline__ void gemm_body(const __half* __restrict__ Ag0,
                                          const __half* __restrict__ Bg0,
                                          float* __restrict__ Cg0,
                                          int K, int ldc)
{
    extern __shared__ char smem_dyn[];
    char* Asm = smem_dyn;
    char* Bsm = smem_dyn + NSTAGE * A_STAGE_B;
    const uint32_t aBase = (uint32_t)__cvta_generic_to_shared(Asm);
    const uint32_t bBase = (uint32_t)__cvta_generic_to_shared(Bsm);

    const int tid   = threadIdx.x;
    const int lane  = tid & 31;
    const int warp  = tid >> 5;
    const int group = lane >> 2;
    const int tig   = lane & 3;
    const int wm = (warp >> 2) * 64;
    const int wn = (warp & 3) * 64;

    const int lj = lane >> 3;
    const int lrr = lane & 7;
    const uint32_t fragOff =
        (uint32_t)(((lj & 1) * 8 + lrr) * ROWB + (lj >> 1) * 16);

    float c[4][8][4];
#pragma unroll
    for (int mt = 0; mt < 4; mt++)
#pragma unroll
        for (int nt = 0; nt < 8; nt++)
#pragma unroll
            for (int q = 0; q < 4; q++) c[mt][nt][q] = 0.0f;

    const int arow  = tid >> 1;
    const int ahalf = tid & 1;
    const uint32_t aOff  = (uint32_t)(arow * ROWB + ahalf * 16);
    const uint32_t bOff0 = aOff;
    const uint32_t bOff1 = (uint32_t)((arow + 128) * ROWB + ahalf * 16);
    const int niter = K >> 4;

    auto load_stage = [&](int st, int ko) {
        const uint32_t aS = aBase + (uint32_t)(st * A_STAGE_B);
        const uint32_t bS = bBase + (uint32_t)(st * B_STAGE_B);
        cp16(aS + aOff,  Ag0 + (size_t)arow * K + ko + ahalf * 8);
        cp16(bS + bOff0, Bg0 + (size_t)arow * K + ko + ahalf * 8);
        cp16(bS + bOff1, Bg0 + (size_t)(arow + 128) * K + ko + ahalf * 8);
        asm volatile("cp.async.commit_group;\n");
    };

    load_stage(0, 0);
    load_stage(1, 16);
    load_stage(2, 32);
    load_stage(3, 48);

    int st = 0, ldst = 4;
    for (int it = 0; it < niter; it++) {
        asm volatile("cp.async.wait_group 3;\n");
        __syncthreads();

        const uint32_t aT = aBase + (uint32_t)(st * A_STAGE_B);
        const uint32_t bT = bBase + (uint32_t)(st * B_STAGE_B);

        uint32_t a[4][4], bf[4][4];
#pragma unroll
        for (int mt = 0; mt < 4; mt++)
            ldsm4(a[mt][0], a[mt][1], a[mt][2], a[mt][3],
                  aT + (uint32_t)((wm + mt * 16) * ROWB) + fragOff);
#pragma unroll
        for (int bt = 0; bt < 4; bt++)
            ldsm4(bf[bt][0], bf[bt][1], bf[bt][2], bf[bt][3],
                  bT + (uint32_t)((wn + bt * 16) * ROWB) + fragOff);

#pragma unroll
        for (int mt = 0; mt < 4; mt++)
#pragma unroll
            for (int nt = 0; nt < 8; nt++) {
                const int bt = nt >> 1, s = nt & 1;
                mma_f16(c[mt][nt], a[mt], bf[bt][s], bf[bt][s + 2]);
            }

        if (it + 4 < niter)
            load_stage(ldst, (it + 4) * 16);
        else
            asm volatile("cp.async.commit_group;\n");

        st   = (st   + 1 == NSTAGE) ? 0 : st + 1;
        ldst = (ldst + 1 == NSTAGE) ? 0 : ldst + 1;
    }

#pragma unroll
    for (int mt = 0; mt < 4; mt++) {
        const int m0 = wm + mt * 16 + group;
#pragma unroll
        for (int nt = 0; nt < 8; nt++) {
            const int n0 = wn + nt * 8 + 2 * tig;
            *(float2*)(Cg0 + (size_t)m0 * ldc + n0) =
                make_float2(c[mt][nt][0], c[mt][nt][1]);
            *(float2*)(Cg0 + (size_t)(m0 + 8) * ldc + n0) =
                make_float2(c[mt][nt][2], c[mt][nt][3]);
        }
    }
}

__global__ void __launch_bounds__(256)
f16_gemm_nt(const __half* __restrict__ A, const __half* __restrict__ B,
            float* __restrict__ C, int K, int ldc)
{
    gemm_body(A + (size_t)blockIdx.y * BM * K,
              B + (size_t)blockIdx.x * BN * K,
              C + (size_t)blockIdx.y * BM * ldc + blockIdx.x * BN,
              K, ldc);
}

// ---------------------------------------------------------------------------
// Sequential recurrence with inline conv, reading inputs from an smem
// double-buffer filled by cp.async (L2-coherent) from the concurrently
// produced proj. Flag-gated per m-tile (= 128 steps of one batch).
// 128 threads: warps 0-1 = f path, warps 2-3 = r path. R6 step structure.
// ---------------------------------------------------------------------------
__device__ void scan_body(const float* proj,
                          const float* __restrict__ cw,
                          const float* __restrict__ sw,
                          float* __restrict__ y, int bh, float* stage)
{
    const int tid  = threadIdx.x;
    const int k    = tid & 63;
    const bool isf = tid < 64;
    const int head = bh & 7;
    const int b    = bh >> 3;

    __shared__ __align__(16) float h_sh[64];
    __shared__ __align__(16) float hr_sh[64];

    unsigned long long wg[32];  // Wf (f-threads) or Wr (r-threads)
    unsigned long long wz[32];  // W  (f-threads only)
    {
        const int gidx = isf ? (NHEADS + head) : (2 * NHEADS + head);
        const float* base = sw + (size_t)gidx * 64 * 64 + k;
#pragma unroll
        for (int i = 0; i < 32; i++)
            wg[i] = pk2(base[(2 * i) * 64], base[(2 * i + 1) * 64]);
        if (isf) {
            const float* bz = sw + (size_t)head * 64 * 64 + k;
#pragma unroll
            for (int i = 0; i < 32; i++)
                wz[i] = pk2(bz[(2 * i) * 64], bz[(2 * i + 1) * 64]);
        }
    }

    // conv weights for channel head*64+k (f-threads only)
    float cw0 = 0.f, cw1 = 0.f, cw2 = 0.f, cw3 = 0.f;
    if (isf) {
        const float* cwp = cw + (size_t)(head * HDIM + k) * 4;
        cw0 = cwp[0]; cw1 = cwp[1]; cw2 = cwp[2]; cw3 = cwp[3];
    }

    if (tid < 64) h_sh[tid] = 0.0f;

    const int* flags = g_flags + b * 32;
    const size_t rowbase = (size_t)b * SEQ;

    // staging: thread covers rows {trow, trow+8, ...}, 16B col slice tq4
    const int trow = tid >> 4;      // 0..7
    const int tq4  = tid & 15;      // 0..15
    const uint32_t stBase = (uint32_t)__cvta_generic_to_shared(stage);

    auto stage_chunk = [&](int ch) {
        const int s0 = ch * CHUNK;
        const uint32_t dst0 = stBase
            + (uint32_t)((ch & 1) * BUF_STRIDE) * 4u;
        const float* src0 = proj + (rowbase + s0) * PROJW
                            + head * HDIM + tq4 * 4;
#pragma unroll
        for (int op = 0; op < 3; op++) {
            const int opoff = op * STATE;   // 0 = xi_raw, 512 = xf, 1024 = xr
#pragma unroll
            for (int i = 0; i < 8; i++) {
                const int row = i * 8 + trow;
                cp16(dst0 + (uint32_t)((op * OP_STRIDE + row * 64 + tq4 * 4) * 4),
                     src0 + (size_t)row * PROJW + opoff);
            }
        }
    };

    // initial: wait tile 0 of this batch, stage chunks 0 and 1
    if (tid == 0) wait_flag(&flags[0]);
    __syncthreads();
    stage_chunk(0); asm volatile("cp.async.commit_group;\n");
    stage_chunk(1); asm volatile("cp.async.commit_group;\n");

    float rm1 = 0.f, rm2 = 0.f, rm3 = 0.f;   // conv rolling window
    float* y_ptr = y + rowbase * STATE + head * HDIM + k;

    const ulonglong2* hp  = (const ulonglong2*)h_sh;
    const ulonglong2* hrp = (const ulonglong2*)hr_sh;

    for (int ch = 0; ch < NCHUNKS; ch++) {
        asm volatile("cp.async.wait_group 1;\n");
        __syncthreads();

        const float* bufp = stage + (ch & 1) * BUF_STRIDE;
        const float* xg_s = bufp + (isf ? OP_STRIDE : 2 * OP_STRIDE) + k;
        const float* xi_s = bufp + k;
        const int sb = ch * CHUNK;

#pragma unroll 4
        for (int js = 0; js < CHUNK; js++) {
            const float xg = xg_s[js * 64];
            float xiv = 0.f;
            if (isf) {
                const float raw = xi_s[js * 64];
                const float a = fmaf(cw3, raw,
                                 fmaf(cw2, rm1, fmaf(cw1, rm2, cw0 * rm3)));
                xiv = a * sigmoid_fast(a);
                rm3 = rm2; rm2 = rm1; rm1 = raw;
            }

            // phase A: gate dot over h (4 chains, LDS.128 broadcast)
            unsigned long long a0 = 0ull, a1 = 0ull, a2 = 0ull, a3 = 0ull;
#pragma unroll
            for (int i = 0; i < 8; i++) {
                ulonglong2 p0 = hp[2 * i];
                ulonglong2 p1 = hp[2 * i + 1];
                fma2(a0, p0.x, wg[4 * i + 0]);
                fma2(a1, p0.y, wg[4 * i + 1]);
                fma2(a2, p1.x, wg[4 * i + 2]);
                fma2(a3, p1.y, wg[4 * i + 3]);
            }
            const float gate =
                sigmoid_fast(hadd2(add2(add2(a0, a1), add2(a2, a3))) + xg);
            const float hk = h_sh[k];
            if (!isf) hr_sh[k] = hk * gate;
            __syncthreads();

            if (isf) {
                unsigned long long z0 = 0ull, z1 = 0ull, z2 = 0ull, z3 = 0ull;
#pragma unroll
                for (int i = 0; i < 8; i++) {
                    ulonglong2 p0 = hrp[2 * i];
                    ulonglong2 p1 = hrp[2 * i + 1];
                    fma2(z0, p0.x, wz[4 * i + 0]);
                    fma2(z1, p0.y, wz[4 * i + 1]);
                    fma2(z2, p1.x, wz[4 * i + 2]);
                    fma2(z3, p1.y, wz[4 * i + 3]);
                }
                const float z =
                    tanh_fast(hadd2(add2(add2(z0, z1), add2(z2, z3))) + xiv);
                const float hn = fmaf(gate, hk - z, z);   // f*h + (1-f)*z
                h_sh[k] = hn;
                y_ptr[(size_t)(sb + js) * STATE] = hn;
            }
            __syncthreads();
        }

        // boundary: stage chunk ch+2 (tile (ch+2)/2) into the buffer just freed
        if (ch + 2 < NCHUNKS) {
            if (tid == 0) wait_flag(&flags[(ch + 2) >> 1]);
            __syncthreads();
            stage_chunk(ch + 2);
        }
        asm volatile("cp.async.commit_group;\n");
    }
}

// ---------------------------------------------------------------------------
// Fused kernel: blocks 0..31 scan (flag-gated, smem-staged inputs);
// blocks 32..1055 full proj GEMM (time-first m-tile order, flag publish).
// ---------------------------------------------------------------------------
__global__ void __launch_bounds__(256)
fused_scan_gemm(float* proj,
                const float* __restrict__ cw,
                const float* __restrict__ sw,
                float* __restrict__ y,
                const __half* __restrict__ xh,
                const __half* __restrict__ winh)
{
    extern __shared__ char smem_dyn[];
    if (blockIdx.x < 32) {
        if (threadIdx.x >= 128) return;
        scan_body(proj, cw, sw, y, blockIdx.x, (float*)smem_dyn);
    } else {
        const int idx = blockIdx.x - 32;
        const int nt = idx & 7;                 // n-tile 0..7
        const int m_order = idx >> 3;           // time-first order
        const int by = (m_order & 3) * 32 + (m_order >> 2);
        gemm_body(xh + (size_t)by * BM * DMODEL,
                  winh + (size_t)nt * BN * DMODEL,
                  proj + (size_t)by * BM * PROJW + nt * BN,
                  DMODEL, PROJW);
        __threadfence();
        __syncthreads();
        if (threadIdx.x == 0) atomicAdd(&g_flags[by], 1);
    }
}

// ---------------------------------------------------------------------------
// Epilogue: v = y * silu(g); rmsnorm; * norm_w; -> fp16 yn (GEMM2's A)
// ---------------------------------------------------------------------------
__global__ void __launch_bounds__(128)
epilogue_kernel(const float* __restrict__ y, const float* __restrict__ proj,
                const float* __restrict__ norm_w, __half* __restrict__ yn)
{
    const int row = blockIdx.x;
    const int tid = threadIdx.x;
    const float* yr = y    + (size_t)row * STATE;
    const float* gr = proj + (size_t)row * PROJW + 3 * STATE;

    float v[4];
    float ss = 0.0f;
#pragma unroll
    for (int q = 0; q < 4; q++) {
        int c = tid + q * 128;
        float g = gr[c];
        float val = yr[c] * g * fsigmoid(g);
        v[q] = val;
        ss += val * val;
    }
#pragma unroll
    for (int off = 16; off > 0; off >>= 1)
        ss += __shfl_xor_sync(0xffffffffu, ss, off);
    __shared__ float red[4];
    if ((tid & 31) == 0) red[tid >> 5] = ss;
    __syncthreads();
    float tot = red[0] + red[1] + red[2] + red[3];
    float scale = rsqrtf(tot * (1.0f / 512.0f) + 1e-6f);
#pragma unroll
    for (int q = 0; q < 4; q++) {
        int c = tid + q * 128;
        yn[(size_t)row * STATE + c] = __float2half_rn(v[q] * scale * norm_w[c]);
    }
}

// ---------------------------------------------------------------------------
// Launch
// ---------------------------------------------------------------------------
extern "C" void kernel_launch(void* const* d_in, const int* in_sizes, int n_in,
                              void* d_out, int out_size)
{
    const float* x      = (const float*)d_in[0];
    const float* w_in   = (const float*)d_in[1];
    const float* conv_w = (const float*)d_in[2];
    const float* sw     = (const float*)d_in[3];
    const float* norm_w = (const float*)d_in[4];
    const float* w_out  = (const float*)d_in[5];
    float* out = (float*)d_out;

    float *proj, *y;
    __half *xh, *winh, *wouth, *ynh;
    cudaGetSymbolAddress((void**)&proj,  g_proj);
    cudaGetSymbolAddress((void**)&y,     g_y);
    cudaGetSymbolAddress((void**)&xh,    g_xh);
    cudaGetSymbolAddress((void**)&winh,  g_winh);
    cudaGetSymbolAddress((void**)&wouth, g_wouth);
    cudaGetSymbolAddress((void**)&ynh,   g_ynh);

    cudaFuncSetAttribute(f16_gemm_nt,
                         cudaFuncAttributeMaxDynamicSharedMemorySize,
                         SMEM_DYN_BYTES);
    cudaFuncSetAttribute(fused_scan_gemm,
                         cudaFuncAttributeMaxDynamicSharedMemorySize,
                         SMEM_DYN_BYTES);

    // 0. reset flags + fp32 -> fp16 conversions
    zero_flags_kernel<<<1, NMTILES>>>();
    f32_to_f16_kernel<<<(ROWS * DMODEL / 8 + 255) / 256, 256>>>(
        x, xh, ROWS * DMODEL / 8);
    f32_to_f16_kernel<<<(PROJW * DMODEL / 8 + 255) / 256, 256>>>(
        w_in, winh, PROJW * DMODEL / 8);
    f32_to_f16_kernel<<<(DMODEL * STATE / 8 + 255) / 256, 256>>>(
        w_out, wouth, DMODEL * STATE / 8);

    // 1. fused: scan (32 blocks, smem-staged + flag-gated)
    //          + full proj GEMM (1024 blocks, flag publish)
    fused_scan_gemm<<<32 + NMTILES * NTILES_N, 256, SMEM_DYN_BYTES>>>(
        proj, conv_w, sw, y, xh, winh);

    // 2. gate + rmsnorm -> ynh (fp16)
    epilogue_kernel<<<ROWS, 128>>>(y, proj, norm_w, ynh);

    // 3. out = yn @ w_out^T  (16384 x 1024 x 512)
    {
        dim3 grid(DMODEL / BN, ROWS / BM);  // 4 x 128
        f16_gemm_nt<<<grid, 256, SMEM_DYN_BYTES>>>(ynh, wouth, out,
                                                   STATE, DMODEL);
    }
}

// round 13
// speedup vs baseline: 1.3393x; 1.0345x over previous
#include <cuda_runtime.h>
#include <cuda_fp16.h>
#include <cuda_bf16.h>
#include <cstdint>

// ---------------------------------------------------------------------------
// Problem constants
// ---------------------------------------------------------------------------
#define BATCH   4
#define SEQ     4096
#define DMODEL  1024
#define NHEADS  8
#define HDIM    64
#define STATE   512            // NHEADS*HDIM
#define PROJW   2048           // 4*STATE
#define ROWS    (BATCH*SEQ)    // 16384

// GEMM tiling: block 128x256, 8 warps of 64x64, fp16 HMMA m16n8k16
#define BM 128
#define BN 256
#define NSTAGE 5
#define ROWB 48                         // padded smem row stride (bytes)
#define A_STAGE_B (BM * ROWB)           // 6144 B
#define B_STAGE_B (BN * ROWB)           // 12288 B
#define GEMM_SMEM_BYTES (NSTAGE * (A_STAGE_B + B_STAGE_B))   // 92160 B

#define NTILES_N 8                      // 2048 / BN
#define NMTILES  128                    // ROWS / BM

// Scan input staging: chunks of 64 steps, 3 operands (xi_raw | xf | xr)
#define CHUNK    64
#define NCHUNKS  (SEQ / CHUNK)          // 64
#define OP_STRIDE  (CHUNK * 64)         // 4096 floats per operand
#define BUF_STRIDE (3 * OP_STRIDE)      // 12288 floats per buffer
#define SCAN_SMEM_BYTES (2 * BUF_STRIDE * 4)   // 98304 B

#define SMEM_DYN_BYTES (SCAN_SMEM_BYTES > GEMM_SMEM_BYTES ? \
                        SCAN_SMEM_BYTES : GEMM_SMEM_BYTES)   // 98304

// Fused grid layout
#define BLK_SCAN0   0
#define BLK_GEMM1   32
#define BLK_EPI     (32 + NMTILES * NTILES_N)          // 1056
#define BLK_GEMM2   (BLK_EPI + NMTILES)                // 1184
#define BLK_TOTAL   (BLK_GEMM2 + NMTILES * 4)          // 1696

// ---------------------------------------------------------------------------
// Scratch (device globals -- no runtime allocation allowed)
// ---------------------------------------------------------------------------
__device__ float  g_proj[(size_t)ROWS * PROJW];   // [xi_raw | xf | xr | g]
__device__ float  g_y   [(size_t)ROWS * STATE];   // recurrence output
__device__ __half g_xh  [(size_t)ROWS * DMODEL];  // x (fp16)
__device__ __half g_winh[(size_t)PROJW * DMODEL]; // w_in (fp16)
__device__ __half g_wouth[(size_t)DMODEL * STATE];// w_out (fp16)
__device__ __half g_ynh [(size_t)ROWS * STATE];   // gated+normed (fp16)
__device__ int    g_flags  [NMTILES];   // proj m-tile done (8 = all n-tiles)
__device__ int    g_yflags [NMTILES];   // y m-tile done (8 = all heads)
__device__ int    g_ynflags[NMTILES];   // ynh m-tile done (1)

// ---------------------------------------------------------------------------
// Helpers
// ---------------------------------------------------------------------------
__device__ __forceinline__ unsigned long long pk2(float lo, float hi) {
    unsigned long long r;
    asm("mov.b64 %0, {%1, %2};" : "=l"(r) : "f"(lo), "f"(hi));
    return r;
}
__device__ __forceinline__ void fma2(unsigned long long& d,
                                     unsigned long long a,
                                     unsigned long long b) {
    asm("fma.rn.f32x2 %0, %1, %2, %0;" : "+l"(d) : "l"(a), "l"(b));
}
__device__ __forceinline__ unsigned long long add2(unsigned long long a,
                                                   unsigned long long b) {
    unsigned long long d;
    asm("add.rn.f32x2 %0, %1, %2;" : "=l"(d) : "l"(a), "l"(b));
    return d;
}
__device__ __forceinline__ float hadd2(unsigned long long v) {
    float a, b;
    asm("mov.b64 {%0, %1}, %2;" : "=f"(a), "=f"(b) : "l"(v));
    return a + b;
}
__device__ __forceinline__ float fsigmoid(float x) {
    return __fdividef(1.0f, 1.0f + __expf(-x));
}
__device__ __forceinline__ float tanh_fast(float x) {
    float y;
    asm("tanh.approx.f32 %0, %1;" : "=f"(y) : "f"(x));
    return y;
}
__device__ __forceinline__ float sigmoid_fast(float x) {
    return fmaf(0.5f, tanh_fast(0.5f * x), 0.5f);
}
__device__ __forceinline__ int ld_acq(const int* p) {
    int v;
    asm volatile("ld.global.acquire.gpu.b32 %0, [%1];" : "=r"(v) : "l"(p));
    return v;
}
__device__ __forceinline__ void wait_flag(const int* p, int target) {
    while (ld_acq(p) < target) { __nanosleep(128); }
}
__device__ __forceinline__ float4 ldcg4(const float* p) {
    float4 v;
    asm volatile("ld.global.cg.v4.f32 {%0,%1,%2,%3}, [%4];"
                 : "=f"(v.x), "=f"(v.y), "=f"(v.z), "=f"(v.w) : "l"(p));
    return v;
}

// ---------------------------------------------------------------------------
// GEMM primitives
// ---------------------------------------------------------------------------
__device__ __forceinline__ void mma_f16(float* c, const uint32_t* a,
                                        uint32_t b0, uint32_t b1) {
    asm volatile(
        "mma.sync.aligned.m16n8k16.row.col.f32.f16.f16.f32 "
        "{%0,%1,%2,%3}, {%4,%5,%6,%7}, {%8,%9}, {%0,%1,%2,%3};\n"
        : "+f"(c[0]), "+f"(c[1]), "+f"(c[2]), "+f"(c[3])
        : "r"(a[0]), "r"(a[1]), "r"(a[2]), "r"(a[3]), "r"(b0), "r"(b1));
}
__device__ __forceinline__ void ldsm4(uint32_t& r0, uint32_t& r1,
                                      uint32_t& r2, uint32_t& r3,
                                      uint32_t addr) {
    asm volatile("ldmatrix.sync.aligned.m8n8.x4.shared.b16 "
                 "{%0,%1,%2,%3}, [%4];"
                 : "=r"(r0), "=r"(r1), "=r"(r2), "=r"(r3) : "r"(addr));
}
__device__ __forceinline__ void cp16(uint32_t dst, const void* src) {
    asm volatile("cp.async.cg.shared.global [%0], [%1], 16;\n"
                 :: "r"(dst), "l"(src));
}

// ---------------------------------------------------------------------------
// Flag reset (graph-replay safe)
// ---------------------------------------------------------------------------
__global__ void zero_flags_kernel() {
    int t = threadIdx.x;     // 128 threads
    g_flags[t] = 0; g_yflags[t] = 0; g_ynflags[t] = 0;
}

// ---------------------------------------------------------------------------
// Pre-pass: fp32 -> fp16 (rn), 8 elems/thread
// ---------------------------------------------------------------------------
__global__ void __launch_bounds__(256)
f32_to_f16_kernel(const float* __restrict__ src, __half* __restrict__ dst,
                  int n8)
{
    int g = blockIdx.x * 256 + threadIdx.x;
    if (g >= n8) return;
    const float4* s = (const float4*)(src + (size_t)g * 8);
    float4 a = s[0], b = s[1];
    __half2 h0 = __floats2half2_rn(a.x, a.y);
    __half2 h1 = __floats2half2_rn(a.z, a.w);
    __half2 h2 = __floats2half2_rn(b.x, b.y);
    __half2 h3 = __floats2half2_rn(b.z, b.w);
    uint4 o;
    o.x = *(uint32_t*)&h0; o.y = *(uint32_t*)&h1;
    o.z = *(uint32_t*)&h2; o.w = *(uint32_t*)&h3;
    *(uint4*)(dst + (size_t)g * 8) = o;
}

// ---------------------------------------------------------------------------
// 128x256 fp16 GEMM body (NT): C[m,n] = sum_k A[m,k]*B[n,k], fp32 accum/out.
// A reads go through cp.async.cg -> L2-coherent (safe for same-kernel producers)
// ---------------------------------------------------------------------------
__device__ __forceinline__ void gemm_body(const __half* __restrict__ Ag0,
                                          const __half* __restrict__ Bg0,
                                          float* __restrict__ Cg0,
                                          int K, int ldc)
{
    extern __shared__ char smem_dyn[];
    char* Asm = smem_dyn;
    char* Bsm = smem_dyn + NSTAGE * A_STAGE_B;
    const uint32_t aBase = (uint32_t)__cvta_generic_to_shared(Asm);
    const uint32_t bBase = (uint32_t)__cvta_generic_to_shared(Bsm);

    const int tid   = threadIdx.x;
    const int lane  = tid & 31;
    const int warp  = tid >> 5;
    const int group = lane >> 2;
    const int tig   = lane & 3;
    const int wm = (warp >> 2) * 64;
    const int wn = (warp & 3) * 64;

    const int lj = lane >> 3;
    const int lrr = lane & 7;
    const uint32_t fragOff =
        (uint32_t)(((lj & 1) * 8 + lrr) * ROWB + (lj >> 1) * 16);

    float c[4][8][4];
#pragma unroll
    for (int mt = 0; mt < 4; mt++)
#pragma unroll
        for (int nt = 0; nt < 8; nt++)
#pragma unroll
            for (int q = 0; q < 4; q++) c[mt][nt][q] = 0.0f;

    const int arow  = tid >> 1;
    const int ahalf = tid & 1;
    const uint32_t aOff  = (uint32_t)(arow * ROWB + ahalf * 16);
    const uint32_t bOff0 = aOff;
    const uint32_t bOff1 = (uint32_t)((arow + 128) * ROWB + ahalf * 16);
    const int niter = K >> 4;

    auto load_stage = [&](int st, int ko) {
        const uint32_t aS = aBase + (uint32_t)(st * A_STAGE_B);
        const uint32_t bS = bBase + (uint32_t)(st * B_STAGE_B);
        cp16(aS + aOff,  Ag0 + (size_t)arow * K + ko + ahalf * 8);
        cp16(bS + bOff0, Bg0 + (size_t)arow * K + ko + ahalf * 8);
        cp16(bS + bOff1, Bg0 + (size_t)(arow + 128) * K + ko + ahalf * 8);
        asm volatile("cp.async.commit_group;\n");
    };

    load_stage(0, 0);
    load_stage(1, 16);
    load_stage(2, 32);
    load_stage(3, 48);

    int st = 0, ldst = 4;
    for (int it = 0; it < niter; it++) {
        asm volatile("cp.async.wait_group 3;\n");
        __syncthreads();

        const uint32_t aT = aBase + (uint32_t)(st * A_STAGE_B);
        const uint32_t bT = bBase + (uint32_t)(st * B_STAGE_B);

        uint32_t a[4][4], bf[4][4];
#pragma unroll
        for (int mt = 0; mt < 4; mt++)
            ldsm4(a[mt][0], a[mt][1], a[mt][2], a[mt][3],
                  aT + (uint32_t)((wm + mt * 16) * ROWB) + fragOff);
#pragma unroll
        for (int bt = 0; bt < 4; bt++)
            ldsm4(bf[bt][0], bf[bt][1], bf[bt][2], bf[bt][3],
                  bT + (uint32_t)((wn + bt * 16) * ROWB) + fragOff);

#pragma unroll
        for (int mt = 0; mt < 4; mt++)
#pragma unroll
            for (int nt = 0; nt < 8; nt++) {
                const int bt = nt >> 1, s = nt & 1;
                mma_f16(c[mt][nt], a[mt], bf[bt][s], bf[bt][s + 2]);
            }

        if (it + 4 < niter)
            load_stage(ldst, (it + 4) * 16);
        else
            asm volatile("cp.async.commit_group;\n");

        st   = (st   + 1 == NSTAGE) ? 0 : st + 1;
        ldst = (ldst + 1 == NSTAGE) ? 0 : ldst + 1;
    }

#pragma unroll
    for (int mt = 0; mt < 4; mt++) {
        const int m0 = wm + mt * 16 + group;
#pragma unroll
        for (int nt = 0; nt < 8; nt++) {
            const int n0 = wn + nt * 8 + 2 * tig;
            *(float2*)(Cg0 + (size_t)m0 * ldc + n0) =
                make_float2(c[mt][nt][0], c[mt][nt][1]);
            *(float2*)(Cg0 + (size_t)(m0 + 8) * ldc + n0) =
                make_float2(c[mt][nt][2], c[mt][nt][3]);
        }
    }
}

// ---------------------------------------------------------------------------
// Sequential recurrence with inline conv; smem-staged inputs (R12 structure);
// publishes y-progress flags every 128 steps.
// ---------------------------------------------------------------------------
__device__ void scan_body(const float* proj,
                          const float* __restrict__ cw,
                          const float* __restrict__ sw,
                          float* __restrict__ y, int bh, float* stage)
{
    const int tid  = threadIdx.x;
    const int k    = tid & 63;
    const bool isf = tid < 64;
    const int head = bh & 7;
    const int b    = bh >> 3;

    __shared__ __align__(16) float h_sh[64];
    __shared__ __align__(16) float hr_sh[64];

    unsigned long long wg[32];  // Wf (f-threads) or Wr (r-threads)
    unsigned long long wz[32];  // W  (f-threads only)
    {
        const int gidx = isf ? (NHEADS + head) : (2 * NHEADS + head);
        const float* base = sw + (size_t)gidx * 64 * 64 + k;
#pragma unroll
        for (int i = 0; i < 32; i++)
            wg[i] = pk2(base[(2 * i) * 64], base[(2 * i + 1) * 64]);
        if (isf) {
            const float* bz = sw + (size_t)head * 64 * 64 + k;
#pragma unroll
            for (int i = 0; i < 32; i++)
                wz[i] = pk2(bz[(2 * i) * 64], bz[(2 * i + 1) * 64]);
        }
    }

    float cw0 = 0.f, cw1 = 0.f, cw2 = 0.f, cw3 = 0.f;
    if (isf) {
        const float* cwp = cw + (size_t)(head * HDIM + k) * 4;
        cw0 = cwp[0]; cw1 = cwp[1]; cw2 = cwp[2]; cw3 = cwp[3];
    }

    if (tid < 64) h_sh[tid] = 0.0f;

    const int* flags = g_flags + b * 32;
    const size_t rowbase = (size_t)b * SEQ;

    const int trow = tid >> 4;      // 0..7
    const int tq4  = tid & 15;      // 0..15
    const uint32_t stBase = (uint32_t)__cvta_generic_to_shared(stage);

    auto stage_chunk = [&](int ch) {
        const int s0 = ch * CHUNK;
        const uint32_t dst0 = stBase
            + (uint32_t)((ch & 1) * BUF_STRIDE) * 4u;
        const float* src0 = proj + (rowbase + s0) * PROJW
                            + head * HDIM + tq4 * 4;
#pragma unroll
        for (int op = 0; op < 3; op++) {
            const int opoff = op * STATE;
#pragma unroll
            for (int i = 0; i < 8; i++) {
                const int row = i * 8 + trow;
                cp16(dst0 + (uint32_t)((op * OP_STRIDE + row * 64 + tq4 * 4) * 4),
                     src0 + (size_t)row * PROJW + opoff);
            }
        }
    };

    if (tid == 0) wait_flag(&flags[0], NTILES_N);
    __syncthreads();
    stage_chunk(0); asm volatile("cp.async.commit_group;\n");
    stage_chunk(1); asm volatile("cp.async.commit_group;\n");

    float rm1 = 0.f, rm2 = 0.f, rm3 = 0.f;
    float* y_ptr = y + rowbase * STATE + head * HDIM + k;

    const ulonglong2* hp  = (const ulonglong2*)h_sh;
    const ulonglong2* hrp = (const ulonglong2*)hr_sh;

    for (int ch = 0; ch < NCHUNKS; ch++) {
        asm volatile("cp.async.wait_group 1;\n");
        __syncthreads();

        const float* bufp = stage + (ch & 1) * BUF_STRIDE;
        const float* xg_s = bufp + (isf ? OP_STRIDE : 2 * OP_STRIDE) + k;
        const float* xi_s = bufp + k;
        const int sb = ch * CHUNK;

#pragma unroll 4
        for (int js = 0; js < CHUNK; js++) {
            const float xg = xg_s[js * 64];
            float xiv = 0.f;
            if (isf) {
                const float raw = xi_s[js * 64];
                const float a = fmaf(cw3, raw,
                                 fmaf(cw2, rm1, fmaf(cw1, rm2, cw0 * rm3)));
                xiv = a * sigmoid_fast(a);
                rm3 = rm2; rm2 = rm1; rm1 = raw;
            }

            unsigned long long a0 = 0ull, a1 = 0ull, a2 = 0ull, a3 = 0ull;
#pragma unroll
            for (int i = 0; i < 8; i++) {
                ulonglong2 p0 = hp[2 * i];
                ulonglong2 p1 = hp[2 * i + 1];
                fma2(a0, p0.x, wg[4 * i + 0]);
                fma2(a1, p0.y, wg[4 * i + 1]);
                fma2(a2, p1.x, wg[4 * i + 2]);
                fma2(a3, p1.y, wg[4 * i + 3]);
            }
            const float gate =
                sigmoid_fast(hadd2(add2(add2(a0, a1), add2(a2, a3))) + xg);
            const float hk = h_sh[k];
            if (!isf) hr_sh[k] = hk * gate;
            __syncthreads();

            if (isf) {
                unsigned long long z0 = 0ull, z1 = 0ull, z2 = 0ull, z3 = 0ull;
#pragma unroll
                for (int i = 0; i < 8; i++) {
                    ulonglong2 p0 = hrp[2 * i];
                    ulonglong2 p1 = hrp[2 * i + 1];
                    fma2(z0, p0.x, wz[4 * i + 0]);
                    fma2(z1, p0.y, wz[4 * i + 1]);
                    fma2(z2, p1.x, wz[4 * i + 2]);
                    fma2(z3, p1.y, wz[4 * i + 3]);
                }
                const float z =
                    tanh_fast(hadd2(add2(add2(z0, z1), add2(z2, z3))) + xiv);
                const float hn = fmaf(gate, hk - z, z);
                h_sh[k] = hn;
                y_ptr[(size_t)(sb + js) * STATE] = hn;
            }
            __syncthreads();
        }

        // publish y progress for the m-tile just completed (every 2 chunks)
        if (ch & 1) {
            __threadfence();
            __syncthreads();
            if (tid == 0) atomicAdd(&g_yflags[b * 32 + (ch >> 1)], 1);
        }

        if (ch + 2 < NCHUNKS) {
            if (tid == 0) wait_flag(&flags[(ch + 2) >> 1], NTILES_N);
            __syncthreads();
            stage_chunk(ch + 2);
        }
        asm volatile("cp.async.commit_group;\n");
    }
}

// ---------------------------------------------------------------------------
// Epilogue body: one m-tile (128 rows). Gated on y + g availability.
// 8 warps x 16 rows; lane covers cols {lane*4 + j*128}. ldcg reads.
// ---------------------------------------------------------------------------
__device__ void epilogue_body(const float* y, const float* proj,
                              const float* __restrict__ norm_w,
                              __half* yn, int by)
{
    const int tid = threadIdx.x;
    if (tid == 0) {
        wait_flag(&g_flags[by], NTILES_N);   // g column of proj ready
        wait_flag(&g_yflags[by], NHEADS);    // y rows ready (8 heads)
    }
    __syncthreads();

    const int w = tid >> 5, lane = tid & 31;
    float nw[16];
#pragma unroll
    for (int j = 0; j < 4; j++) {
        float4 t = *(const float4*)(norm_w + lane * 4 + j * 128);
        nw[4 * j + 0] = t.x; nw[4 * j + 1] = t.y;
        nw[4 * j + 2] = t.z; nw[4 * j + 3] = t.w;
    }

    for (int rr = 0; rr < 16; rr++) {
        const int row = by * BM + w * 16 + rr;
        const float* yr = y    + (size_t)row * STATE;
        const float* gr = proj + (size_t)row * PROJW + 3 * STATE;
        float v[16];
        float ss = 0.0f;
#pragma unroll
        for (int j = 0; j < 4; j++) {
            float4 yv = ldcg4(yr + lane * 4 + j * 128);
            float4 gv = ldcg4(gr + lane * 4 + j * 128);
            float v0 = yv.x * gv.x * fsigmoid(gv.x);
            float v1 = yv.y * gv.y * fsigmoid(gv.y);
            float v2 = yv.z * gv.z * fsigmoid(gv.z);
            float v3 = yv.w * gv.w * fsigmoid(gv.w);
            v[4 * j + 0] = v0; v[4 * j + 1] = v1;
            v[4 * j + 2] = v2; v[4 * j + 3] = v3;
            ss += v0 * v0 + v1 * v1 + v2 * v2 + v3 * v3;
        }
#pragma unroll
        for (int off = 16; off > 0; off >>= 1)
            ss += __shfl_xor_sync(0xffffffffu, ss, off);
        const float scale = rsqrtf(ss * (1.0f / 512.0f) + 1e-6f);
        __half* outr = yn + (size_t)row * STATE;
#pragma unroll
        for (int j = 0; j < 4; j++) {
            __half2 h0 = __floats2half2_rn(v[4 * j + 0] * scale * nw[4 * j + 0],
                                           v[4 * j + 1] * scale * nw[4 * j + 1]);
            __half2 h1 = __floats2half2_rn(v[4 * j + 2] * scale * nw[4 * j + 2],
                                           v[4 * j + 3] * scale * nw[4 * j + 3]);
            uint2 o;
            o.x = *(uint32_t*)&h0; o.y = *(uint32_t*)&h1;
            *(uint2*)(outr + lane * 4 + j * 128) = o;
        }
    }

    __threadfence();
    __syncthreads();
    if (tid == 0) atomicAdd(&g_ynflags[by], 1);
}

// ---------------------------------------------------------------------------
// Fused kernel:
//   blocks [0,32)            : scan (flag-gated, smem-staged inputs)
//   blocks [32,1056)         : proj GEMM (time-first m-tiles, flag publish)
//   blocks [1056,1184)       : epilogue m-tiles (gated on y + g)
//   blocks [1184,1696)       : out GEMM m/n-tiles (gated on ynh)
// Dependencies flow strictly forward in block index -> deadlock-free.
// ---------------------------------------------------------------------------
__global__ void __launch_bounds__(256)
fused_all(float* proj,
          const float* __restrict__ cw,
          const float* __restrict__ sw,
          float* __restrict__ y,
          const __half* __restrict__ xh,
          const __half* __restrict__ winh,
          const float* __restrict__ norm_w,
          __half* ynh,
          const __half* __restrict__ wouth,
          float* __restrict__ out)
{
    extern __shared__ char smem_dyn[];
    const int bx = blockIdx.x;
    if (bx < BLK_GEMM1) {
        if (threadIdx.x >= 128) return;
        scan_body(proj, cw, sw, y, bx, (float*)smem_dyn);
    } else if (bx < BLK_EPI) {
        const int idx = bx - BLK_GEMM1;
        const int nt = idx & 7;
        const int m_order = idx >> 3;
        const int by = (m_order & 3) * 32 + (m_order >> 2);
        gemm_body(xh + (size_t)by * BM * DMODEL,
                  winh + (size_t)nt * BN * DMODEL,
                  proj + (size_t)by * BM * PROJW + nt * BN,
                  DMODEL, PROJW);
        __threadfence();
        __syncthreads();
        if (threadIdx.x == 0) atomicAdd(&g_flags[by], 1);
    } else if (bx < BLK_GEMM2) {
        const int m_order = bx - BLK_EPI;
        const int by = (m_order & 3) * 32 + (m_order >> 2);
        epilogue_body(y, proj, norm_w, ynh, by);
    } else {
        const int idx = bx - BLK_GEMM2;
        const int nt = idx & 3;
        const int m_order = idx >> 2;
        const int by = (m_order & 3) * 32 + (m_order >> 2);
        if (threadIdx.x == 0) wait_flag(&g_ynflags[by], 1);
        __syncthreads();
        gemm_body(ynh + (size_t)by * BM * STATE,
                  wouth + (size_t)nt * BN * STATE,
                  out + (size_t)by * BM * DMODEL + nt * BN,
                  STATE, DMODEL);
    }
}

// ---------------------------------------------------------------------------
// Launch
// ---------------------------------------------------------------------------
extern "C" void kernel_launch(void* const* d_in, const int* in_sizes, int n_in,
                              void* d_out, int out_size)
{
    const float* x      = (const float*)d_in[0];
    const float* w_in   = (const float*)d_in[1];
    const float* conv_w = (const float*)d_in[2];
    const float* sw     = (const float*)d_in[3];
    const float* norm_w = (const float*)d_in[4];
    const float* w_out  = (const float*)d_in[5];
    float* out = (float*)d_out;

    float *proj, *y;
    __half *xh, *winh, *wouth, *ynh;
    cudaGetSymbolAddress((void**)&proj,  g_proj);
    cudaGetSymbolAddress((void**)&y,     g_y);
    cudaGetSymbolAddress((void**)&xh,    g_xh);
    cudaGetSymbolAddress((void**)&winh,  g_winh);
    cudaGetSymbolAddress((void**)&wouth, g_wouth);
    cudaGetSymbolAddress((void**)&ynh,   g_ynh);

    cudaFuncSetAttribute(fused_all,
                         cudaFuncAttributeMaxDynamicSharedMemorySize,
                         SMEM_DYN_BYTES);

    // 0. reset flags + fp32 -> fp16 conversions
    zero_flags_kernel<<<1, NMTILES>>>();
    f32_to_f16_kernel<<<(ROWS * DMODEL / 8 + 255) / 256, 256>>>(
        x, xh, ROWS * DMODEL / 8);
    f32_to_f16_kernel<<<(PROJW * DMODEL / 8 + 255) / 256, 256>>>(
        w_in, winh, PROJW * DMODEL / 8);
    f32_to_f16_kernel<<<(DMODEL * STATE / 8 + 255) / 256, 256>>>(
        w_out, wouth, DMODEL * STATE / 8);

    // 1. fully fused pipeline: proj GEMM -> scan(+conv) -> epilogue -> out GEMM
    fused_all<<<BLK_TOTAL, 256, SMEM_DYN_BYTES>>>(
        proj, conv_w, sw, y, xh, winh, norm_w, ynh, wouth, out);
}

// round 14
// speedup vs baseline: 1.4262x; 1.0649x over previous
#include <cuda_runtime.h>
#include <cuda_fp16.h>
#include <cuda_bf16.h>
#include <cstdint>

// ---------------------------------------------------------------------------
// Problem constants
// ---------------------------------------------------------------------------
#define BATCH   4
#define SEQ     4096
#define DMODEL  1024
#define NHEADS  8
#define HDIM    64
#define STATE   512            // NHEADS*HDIM
#define PROJW   2048           // 4*STATE
#define ROWS    (BATCH*SEQ)    // 16384

// GEMM tiling: block 128x256, 8 warps of 64x64, fp16 HMMA m16n8k16
#define BM 128
#define BN 256
#define NSTAGE 5
#define ROWB 48                         // padded smem row stride (bytes)
#define A_STAGE_B (BM * ROWB)           // 6144 B
#define B_STAGE_B (BN * ROWB)           // 12288 B
#define GEMM_SMEM_BYTES (NSTAGE * (A_STAGE_B + B_STAGE_B))   // 92160 B

#define NTILES_N 8                      // 2048 / BN
#define NMTILES  128                    // ROWS / BM

// Scan input staging: chunks of 64 steps, 3 operands (xi_raw | xf | xr)
#define CHUNK    64
#define NCHUNKS  (SEQ / CHUNK)          // 64
#define OP_STRIDE  (CHUNK * 64)         // 4096 floats per operand
#define BUF_STRIDE (3 * OP_STRIDE)      // 12288 floats per buffer
#define SCAN_SMEM_BYTES (2 * BUF_STRIDE * 4)   // 98304 B

#define SMEM_DYN_BYTES (SCAN_SMEM_BYTES > GEMM_SMEM_BYTES ? \
                        SCAN_SMEM_BYTES : GEMM_SMEM_BYTES)   // 98304

// Fused grid layout
#define BLK_SCAN0   0
#define BLK_GEMM1   32
#define BLK_EPI     (32 + NMTILES * NTILES_N)          // 1056
#define BLK_GEMM2   (BLK_EPI + NMTILES)                // 1184
#define BLK_TOTAL   (BLK_GEMM2 + NMTILES * 4)          // 1696

// Merged conversion sizes (groups of 8 floats)
#define CVT_N1 (ROWS * DMODEL / 8)      // x      : 2097152
#define CVT_N2 (PROJW * DMODEL / 8)     // w_in   : 262144
#define CVT_N3 (DMODEL * STATE / 8)     // w_out  : 65536
#define CVT_TOTAL (CVT_N1 + CVT_N2 + CVT_N3)

// ---------------------------------------------------------------------------
// Scratch (device globals -- no runtime allocation allowed)
// ---------------------------------------------------------------------------
__device__ float  g_proj[(size_t)ROWS * PROJW];   // [xi_raw | xf | xr | g]
__device__ float  g_y   [(size_t)ROWS * STATE];   // recurrence output
__device__ __half g_xh  [(size_t)ROWS * DMODEL];  // x (fp16)
__device__ __half g_winh[(size_t)PROJW * DMODEL]; // w_in (fp16)
__device__ __half g_wouth[(size_t)DMODEL * STATE];// w_out (fp16)
__device__ __half g_ynh [(size_t)ROWS * STATE];   // gated+normed (fp16)
__device__ int    g_flags  [NMTILES];   // proj m-tile done (8 = all n-tiles)
__device__ int    g_yflags [NMTILES];   // y m-tile done (8 = all heads)
__device__ int    g_ynflags[NMTILES];   // ynh m-tile done (1)

// ---------------------------------------------------------------------------
// Helpers
// ---------------------------------------------------------------------------
__device__ __forceinline__ unsigned long long pk2(float lo, float hi) {
    unsigned long long r;
    asm("mov.b64 %0, {%1, %2};" : "=l"(r) : "f"(lo), "f"(hi));
    return r;
}
__device__ __forceinline__ void fma2(unsigned long long& d,
                                     unsigned long long a,
                                     unsigned long long b) {
    asm("fma.rn.f32x2 %0, %1, %2, %0;" : "+l"(d) : "l"(a), "l"(b));
}
__device__ __forceinline__ unsigned long long add2(unsigned long long a,
                                                   unsigned long long b) {
    unsigned long long d;
    asm("add.rn.f32x2 %0, %1, %2;" : "=l"(d) : "l"(a), "l"(b));
    return d;
}
__device__ __forceinline__ float hadd2(unsigned long long v) {
    float a, b;
    asm("mov.b64 {%0, %1}, %2;" : "=f"(a), "=f"(b) : "l"(v));
    return a + b;
}
__device__ __forceinline__ float fsigmoid(float x) {
    return __fdividef(1.0f, 1.0f + __expf(-x));
}
__device__ __forceinline__ float tanh_fast(float x) {
    float y;
    asm("tanh.approx.f32 %0, %1;" : "=f"(y) : "f"(x));
    return y;
}
__device__ __forceinline__ float sigmoid_fast(float x) {
    return fmaf(0.5f, tanh_fast(0.5f * x), 0.5f);
}
__device__ __forceinline__ int ld_acq(const int* p) {
    int v;
    asm volatile("ld.global.acquire.gpu.b32 %0, [%1];" : "=r"(v) : "l"(p));
    return v;
}
__device__ __forceinline__ void wait_flag(const int* p, int target) {
    while (ld_acq(p) < target) { __nanosleep(128); }
}
__device__ __forceinline__ float4 ldcg4(const float* p) {
    float4 v;
    asm volatile("ld.global.cg.v4.f32 {%0,%1,%2,%3}, [%4];"
                 : "=f"(v.x), "=f"(v.y), "=f"(v.z), "=f"(v.w) : "l"(p));
    return v;
}

// ---------------------------------------------------------------------------
// GEMM primitives
// ---------------------------------------------------------------------------
__device__ __forceinline__ void mma_f16(float* c, const uint32_t* a,
                                        uint32_t b0, uint32_t b1) {
    asm volatile(
        "mma.sync.aligned.m16n8k16.row.col.f32.f16.f16.f32 "
        "{%0,%1,%2,%3}, {%4,%5,%6,%7}, {%8,%9}, {%0,%1,%2,%3};\n"
        : "+f"(c[0]), "+f"(c[1]), "+f"(c[2]), "+f"(c[3])
        : "r"(a[0]), "r"(a[1]), "r"(a[2]), "r"(a[3]), "r"(b0), "r"(b1));
}
__device__ __forceinline__ void ldsm4(uint32_t& r0, uint32_t& r1,
                                      uint32_t& r2, uint32_t& r3,
                                      uint32_t addr) {
    asm volatile("ldmatrix.sync.aligned.m8n8.x4.shared.b16 "
                 "{%0,%1,%2,%3}, [%4];"
                 : "=r"(r0), "=r"(r1), "=r"(r2), "=r"(r3) : "r"(addr));
}
__device__ __forceinline__ void cp16(uint32_t dst, const void* src) {
    asm volatile("cp.async.cg.shared.global [%0], [%1], 16;\n"
                 :: "r"(dst), "l"(src));
}

// ---------------------------------------------------------------------------
// Flag reset (graph-replay safe)
// ---------------------------------------------------------------------------
__global__ void zero_flags_kernel() {
    int t = threadIdx.x;     // 128 threads
    g_flags[t] = 0; g_yflags[t] = 0; g_ynflags[t] = 0;
}

// ---------------------------------------------------------------------------
// Merged pre-pass: fp32 -> fp16 (rn) for x, w_in, w_out in one launch
// ---------------------------------------------------------------------------
__global__ void __launch_bounds__(256)
convert_all_kernel(const float* __restrict__ x, __half* __restrict__ xh,
                   const float* __restrict__ w_in, __half* __restrict__ winh,
                   const float* __restrict__ w_out, __half* __restrict__ wouth)
{
    int g = blockIdx.x * 256 + threadIdx.x;
    const float* src;
    __half* dst;
    if (g < CVT_N1) {
        src = x + (size_t)g * 8;            dst = xh + (size_t)g * 8;
    } else if (g < CVT_N1 + CVT_N2) {
        int h8 = g - CVT_N1;
        src = w_in + (size_t)h8 * 8;        dst = winh + (size_t)h8 * 8;
    } else if (g < CVT_TOTAL) {
        int h8 = g - CVT_N1 - CVT_N2;
        src = w_out + (size_t)h8 * 8;       dst = wouth + (size_t)h8 * 8;
    } else {
        return;
    }
    const float4* s = (const float4*)src;
    float4 a = s[0], b = s[1];
    __half2 h0 = __floats2half2_rn(a.x, a.y);
    __half2 h1 = __floats2half2_rn(a.z, a.w);
    __half2 h2 = __floats2half2_rn(b.x, b.y);
    __half2 h3 = __floats2half2_rn(b.z, b.w);
    uint4 o;
    o.x = *(uint32_t*)&h0; o.y = *(uint32_t*)&h1;
    o.z = *(uint32_t*)&h2; o.w = *(uint32_t*)&h3;
    *(uint4*)dst = o;
}

// ---------------------------------------------------------------------------
// 128x256 fp16 GEMM body (NT): C[m,n] = sum_k A[m,k]*B[n,k], fp32 accum/out.
// A reads go through cp.async.cg -> L2-coherent (safe for same-kernel producers)
// ---------------------------------------------------------------------------
__device__ __forceinline__ void gemm_body(const __half* __restrict__ Ag0,
                                          const __half* __restrict__ Bg0,
                                          float* __restrict__ Cg0,
                                          int K, int ldc)
{
    extern __shared__ char smem_dyn[];
    char* Asm = smem_dyn;
    char* Bsm = smem_dyn + NSTAGE * A_STAGE_B;
    const uint32_t aBase = (uint32_t)__cvta_generic_to_shared(Asm);
    const uint32_t bBase = (uint32_t)__cvta_generic_to_shared(Bsm);

    const int tid   = threadIdx.x;
    const int lane  = tid & 31;
    const int warp  = tid >> 5;
    const int group = lane >> 2;
    const int tig   = lane & 3;
    const int wm = (warp >> 2) * 64;
    const int wn = (warp & 3) * 64;

    const int lj = lane >> 3;
    const int lrr = lane & 7;
    const uint32_t fragOff =
        (uint32_t)(((lj & 1) * 8 + lrr) * ROWB + (lj >> 1) * 16);

    float c[4][8][4];
#pragma unroll
    for (int mt = 0; mt < 4; mt++)
#pragma unroll
        for (int nt = 0; nt < 8; nt++)
#pragma unroll
            for (int q = 0; q < 4; q++) c[mt][nt][q] = 0.0f;

    const int arow  = tid >> 1;
    const int ahalf = tid & 1;
    const uint32_t aOff  = (uint32_t)(arow * ROWB + ahalf * 16);
    const uint32_t bOff0 = aOff;
    const uint32_t bOff1 = (uint32_t)((arow + 128) * ROWB + ahalf * 16);
    const int niter = K >> 4;

    auto load_stage = [&](int st, int ko) {
        const uint32_t aS = aBase + (uint32_t)(st * A_STAGE_B);
        const uint32_t bS = bBase + (uint32_t)(st * B_STAGE_B);
        cp16(aS + aOff,  Ag0 + (size_t)arow * K + ko + ahalf * 8);
        cp16(bS + bOff0, Bg0 + (size_t)arow * K + ko + ahalf * 8);
        cp16(bS + bOff1, Bg0 + (size_t)(arow + 128) * K + ko + ahalf * 8);
        asm volatile("cp.async.commit_group;\n");
    };

    load_stage(0, 0);
    load_stage(1, 16);
    load_stage(2, 32);
    load_stage(3, 48);

    int st = 0, ldst = 4;
    for (int it = 0; it < niter; it++) {
        asm volatile("cp.async.wait_group 3;\n");
        __syncthreads();

        const uint32_t aT = aBase + (uint32_t)(st * A_STAGE_B);
        const uint32_t bT = bBase + (uint32_t)(st * B_STAGE_B);

        uint32_t a[4][4], bf[4][4];
#pragma unroll
        for (int mt = 0; mt < 4; mt++)
            ldsm4(a[mt][0], a[mt][1], a[mt][2], a[mt][3],
                  aT + (uint32_t)((wm + mt * 16) * ROWB) + fragOff);
#pragma unroll
        for (int bt = 0; bt < 4; bt++)
            ldsm4(bf[bt][0], bf[bt][1], bf[bt][2], bf[bt][3],
                  bT + (uint32_t)((wn + bt * 16) * ROWB) + fragOff);

#pragma unroll
        for (int mt = 0; mt < 4; mt++)
#pragma unroll
            for (int nt = 0; nt < 8; nt++) {
                const int bt = nt >> 1, s = nt & 1;
                mma_f16(c[mt][nt], a[mt], bf[bt][s], bf[bt][s + 2]);
            }

        if (it + 4 < niter)
            load_stage(ldst, (it + 4) * 16);
        else
            asm volatile("cp.async.commit_group;\n");

        st   = (st   + 1 == NSTAGE) ? 0 : st + 1;
        ldst = (ldst + 1 == NSTAGE) ? 0 : ldst + 1;
    }

#pragma unroll
    for (int mt = 0; mt < 4; mt++) {
        const int m0 = wm + mt * 16 + group;
#pragma unroll
        for (int nt = 0; nt < 8; nt++) {
            const int n0 = wn + nt * 8 + 2 * tig;
            *(float2*)(Cg0 + (size_t)m0 * ldc + n0) =
                make_float2(c[mt][nt][0], c[mt][nt][1]);
            *(float2*)(Cg0 + (size_t)(m0 + 8) * ldc + n0) =
                make_float2(c[mt][nt][2], c[mt][nt][3]);
        }
    }
}

// ---------------------------------------------------------------------------
// Sequential recurrence; smem-staged inputs; conv+silu computed by the
// (otherwise idle) r-warps in phase B one step ahead, handed to f via a
// 2-slot xi_sh ping-pong. y store moved after barrier 2.
// ---------------------------------------------------------------------------
__device__ void scan_body(const float* proj,
                          const float* __restrict__ cw,
                          const float* __restrict__ sw,
                          float* __restrict__ y, int bh, float* stage)
{
    const int tid  = threadIdx.x;
    const int k    = tid & 63;
    const bool isf = tid < 64;
    const int head = bh & 7;
    const int b    = bh >> 3;

    __shared__ __align__(16) float h_sh[64];
    __shared__ __align__(16) float hr_sh[64];
    __shared__ __align__(16) float xi_sh[2][64];   // conv+silu handoff

    unsigned long long wg[32];  // Wf (f-threads) or Wr (r-threads)
    unsigned long long wz[32];  // W  (f-threads only)
    {
        const int gidx = isf ? (NHEADS + head) : (2 * NHEADS + head);
        const float* base = sw + (size_t)gidx * 64 * 64 + k;
#pragma unroll
        for (int i = 0; i < 32; i++)
            wg[i] = pk2(base[(2 * i) * 64], base[(2 * i + 1) * 64]);
        if (isf) {
            const float* bz = sw + (size_t)head * 64 * 64 + k;
#pragma unroll
            for (int i = 0; i < 32; i++)
                wz[i] = pk2(bz[(2 * i) * 64], bz[(2 * i + 1) * 64]);
        }
    }

    // conv weights + rolling window: r-threads only
    float cw0 = 0.f, cw1 = 0.f, cw2 = 0.f, cw3 = 0.f;
    if (!isf) {
        const float* cwp = cw + (size_t)(head * HDIM + k) * 4;
        cw0 = cwp[0]; cw1 = cwp[1]; cw2 = cwp[2]; cw3 = cwp[3];
    }
    float rm1 = 0.f, rm2 = 0.f, rm3 = 0.f;

    if (tid < 64) h_sh[tid] = 0.0f;

    const int* flags = g_flags + b * 32;
    const size_t rowbase = (size_t)b * SEQ;

    const int trow = tid >> 4;      // 0..7
    const int tq4  = tid & 15;      // 0..15
    const uint32_t stBase = (uint32_t)__cvta_generic_to_shared(stage);

    auto stage_chunk = [&](int ch) {
        const int s0 = ch * CHUNK;
        const uint32_t dst0 = stBase
            + (uint32_t)((ch & 1) * BUF_STRIDE) * 4u;
        const float* src0 = proj + (rowbase + s0) * PROJW
                            + head * HDIM + tq4 * 4;
#pragma unroll
        for (int op = 0; op < 3; op++) {
            const int opoff = op * STATE;
#pragma unroll
            for (int i = 0; i < 8; i++) {
                const int row = i * 8 + trow;
                cp16(dst0 + (uint32_t)((op * OP_STRIDE + row * 64 + tq4 * 4) * 4),
                     src0 + (size_t)row * PROJW + opoff);
            }
        }
    };

    if (tid == 0) wait_flag(&flags[0], NTILES_N);
    __syncthreads();
    stage_chunk(0); asm volatile("cp.async.commit_group;\n");
    stage_chunk(1); asm volatile("cp.async.commit_group;\n");

    float* y_ptr = y + rowbase * STATE + head * HDIM + k;

    const ulonglong2* hp  = (const ulonglong2*)h_sh;
    const ulonglong2* hrp = (const ulonglong2*)hr_sh;

    for (int ch = 0; ch < NCHUNKS; ch++) {
        asm volatile("cp.async.wait_group 1;\n");
        __syncthreads();

        const float* bufp = stage + (ch & 1) * BUF_STRIDE;
        const float* xg_s = bufp + (isf ? OP_STRIDE : 2 * OP_STRIDE) + k;
        const float* xi_raw_s = bufp + k;     // op 0: raw xi
        const int sb = ch * CHUNK;

        // chunk top: r computes conv+silu for step 0 (visible after bar1 of js=0)
        if (!isf) {
            const float raw = xi_raw_s[0];
            const float a = fmaf(cw3, raw,
                             fmaf(cw2, rm1, fmaf(cw1, rm2, cw0 * rm3)));
            xi_sh[0][k] = a * sigmoid_fast(a);
            rm3 = rm2; rm2 = rm1; rm1 = raw;
        }

#pragma unroll 4
        for (int js = 0; js < CHUNK; js++) {
            const float xg = xg_s[js * 64];

            // phase A: gate dot over h (4 chains, LDS.128 broadcast)
            unsigned long long a0 = 0ull, a1 = 0ull, a2 = 0ull, a3 = 0ull;
#pragma unroll
            for (int i = 0; i < 8; i++) {
                ulonglong2 p0 = hp[2 * i];
                ulonglong2 p1 = hp[2 * i + 1];
                fma2(a0, p0.x, wg[4 * i + 0]);
                fma2(a1, p0.y, wg[4 * i + 1]);
                fma2(a2, p1.x, wg[4 * i + 2]);
                fma2(a3, p1.y, wg[4 * i + 3]);
            }
            const float gate =
                sigmoid_fast(hadd2(add2(add2(a0, a1), add2(a2, a3))) + xg);
            const float hk = h_sh[k];
            if (!isf) hr_sh[k] = hk * gate;
            __syncthreads();                       // bar1: hr (+xi) visible

            float hn = 0.0f;
            if (isf) {
                // phase B (f): z matvec over h*r
                unsigned long long z0 = 0ull, z1 = 0ull, z2 = 0ull, z3 = 0ull;
#pragma unroll
                for (int i = 0; i < 8; i++) {
                    ulonglong2 p0 = hrp[2 * i];
                    ulonglong2 p1 = hrp[2 * i + 1];
                    fma2(z0, p0.x, wz[4 * i + 0]);
                    fma2(z1, p0.y, wz[4 * i + 1]);
                    fma2(z2, p1.x, wz[4 * i + 2]);
                    fma2(z3, p1.y, wz[4 * i + 3]);
                }
                const float xiv = xi_sh[js & 1][k];
                const float z =
                    tanh_fast(hadd2(add2(add2(z0, z1), add2(z2, z3))) + xiv);
                hn = fmaf(gate, hk - z, z);        // f*h + (1-f)*z
                h_sh[k] = hn;
            } else if (js < CHUNK - 1) {
                // phase B (r): conv+silu for step js+1 into the other slot
                const float raw = xi_raw_s[(js + 1) * 64];
                const float a = fmaf(cw3, raw,
                                 fmaf(cw2, rm1, fmaf(cw1, rm2, cw0 * rm3)));
                xi_sh[(js + 1) & 1][k] = a * sigmoid_fast(a);
                rm3 = rm2; rm2 = rm1; rm1 = raw;
            }
            __syncthreads();                       // bar2: new h visible

            if (isf) y_ptr[(size_t)(sb + js) * STATE] = hn;  // off-path store
        }

        // publish y progress for the m-tile just completed (every 2 chunks)
        if (ch & 1) {
            __threadfence();
            __syncthreads();
            if (tid == 0) atomicAdd(&g_yflags[b * 32 + (ch >> 1)], 1);
        }

        if (ch + 2 < NCHUNKS) {
            if (tid == 0) wait_flag(&flags[(ch + 2) >> 1], NTILES_N);
            __syncthreads();
            stage_chunk(ch + 2);
        }
        asm volatile("cp.async.commit_group;\n");
    }
}

// ---------------------------------------------------------------------------
// Epilogue body: one m-tile (128 rows). Gated on y + g availability.
// ---------------------------------------------------------------------------
__device__ void epilogue_body(const float* y, const float* proj,
                              const float* __restrict__ norm_w,
                              __half* yn, int by)
{
    const int tid = threadIdx.x;
    if (tid == 0) {
        wait_flag(&g_flags[by], NTILES_N);   // g column of proj ready
        wait_flag(&g_yflags[by], NHEADS);    // y rows ready (8 heads)
    }
    __syncthreads();

    const int w = tid >> 5, lane = tid & 31;
    float nw[16];
#pragma unroll
    for (int j = 0; j < 4; j++) {
        float4 t = *(const float4*)(norm_w + lane * 4 + j * 128);
        nw[4 * j + 0] = t.x; nw[4 * j + 1] = t.y;
        nw[4 * j + 2] = t.z; nw[4 * j + 3] = t.w;
    }

    for (int rr = 0; rr < 16; rr++) {
        const int row = by * BM + w * 16 + rr;
        const float* yr = y    + (size_t)row * STATE;
        const float* gr = proj + (size_t)row * PROJW + 3 * STATE;
        float v[16];
        float ss = 0.0f;
#pragma unroll
        for (int j = 0; j < 4; j++) {
            float4 yv = ldcg4(yr + lane * 4 + j * 128);
            float4 gv = ldcg4(gr + lane * 4 + j * 128);
            float v0 = yv.x * gv.x * fsigmoid(gv.x);
            float v1 = yv.y * gv.y * fsigmoid(gv.y);
            float v2 = yv.z * gv.z * fsigmoid(gv.z);
            float v3 = yv.w * gv.w * fsigmoid(gv.w);
            v[4 * j + 0] = v0; v[4 * j + 1] = v1;
            v[4 * j + 2] = v2; v[4 * j + 3] = v3;
            ss += v0 * v0 + v1 * v1 + v2 * v2 + v3 * v3;
        }
#pragma unroll
        for (int off = 16; off > 0; off >>= 1)
            ss += __shfl_xor_sync(0xffffffffu, ss, off);
        const float scale = rsqrtf(ss * (1.0f / 512.0f) + 1e-6f);
        __half* outr = yn + (size_t)row * STATE;
#pragma unroll
        for (int j = 0; j < 4; j++) {
            __half2 h0 = __floats2half2_rn(v[4 * j + 0] * scale * nw[4 * j + 0],
                                           v[4 * j + 1] * scale * nw[4 * j + 1]);
            __half2 h1 = __floats2half2_rn(v[4 * j + 2] * scale * nw[4 * j + 2],
                                           v[4 * j + 3] * scale * nw[4 * j + 3]);
            uint2 o;
            o.x = *(uint32_t*)&h0; o.y = *(uint32_t*)&h1;
            *(uint2*)(outr + lane * 4 + j * 128) = o;
        }
    }

    __threadfence();
    __syncthreads();
    if (tid == 0) atomicAdd(&g_ynflags[by], 1);
}

// ---------------------------------------------------------------------------
// Fused kernel:
//   blocks [0,32)      : scan (flag-gated, smem-staged inputs)
//   blocks [32,1056)   : proj GEMM (time-first m-tiles, flag publish)
//   blocks [1056,1184) : epilogue m-tiles (gated on y + g)
//   blocks [1184,1696) : out GEMM m/n-tiles (gated on ynh)
// Dependencies flow strictly forward in block index -> deadlock-free.
// ---------------------------------------------------------------------------
__global__ void __launch_bounds__(256)
fused_all(float* proj,
          const float* __restrict__ cw,
          const float* __restrict__ sw,
          float* __restrict__ y,
          const __half* __restrict__ xh,
          const __half* __restrict__ winh,
          const float* __restrict__ norm_w,
          __half* ynh,
          const __half* __restrict__ wouth,
          float* __restrict__ out)
{
    extern __shared__ char smem_dyn[];
    const int bx = blockIdx.x;
    if (bx < BLK_GEMM1) {
        if (threadIdx.x >= 128) return;
        scan_body(proj, cw, sw, y, bx, (float*)smem_dyn);
    } else if (bx < BLK_EPI) {
        const int idx = bx - BLK_GEMM1;
        const int nt = idx & 7;
        const int m_order = idx >> 3;
        const int by = (m_order & 3) * 32 + (m_order >> 2);
        gemm_body(xh + (size_t)by * BM * DMODEL,
                  winh + (size_t)nt * BN * DMODEL,
                  proj + (size_t)by * BM * PROJW + nt * BN,
                  DMODEL, PROJW);
        __threadfence();
        __syncthreads();
        if (threadIdx.x == 0) atomicAdd(&g_flags[by], 1);
    } else if (bx < BLK_GEMM2) {
        const int m_order = bx - BLK_EPI;
        const int by = (m_order & 3) * 32 + (m_order >> 2);
        epilogue_body(y, proj, norm_w, ynh, by);
    } else {
        const int idx = bx - BLK_GEMM2;
        const int nt = idx & 3;
        const int m_order = idx >> 2;
        const int by = (m_order & 3) * 32 + (m_order >> 2);
        if (threadIdx.x == 0) wait_flag(&g_ynflags[by], 1);
        __syncthreads();
        gemm_body(ynh + (size_t)by * BM * STATE,
                  wouth + (size_t)nt * BN * STATE,
                  out + (size_t)by * BM * DMODEL + nt * BN,
                  STATE, DMODEL);
    }
}

// ---------------------------------------------------------------------------
// Launch
// ---------------------------------------------------------------------------
extern "C" void kernel_launch(void* const* d_in, const int* in_sizes, int n_in,
                              void* d_out, int out_size)
{
    const float* x      = (const float*)d_in[0];
    const float* w_in   = (const float*)d_in[1];
    const float* conv_w = (const float*)d_in[2];
    const float* sw     = (const float*)d_in[3];
    const float* norm_w = (const float*)d_in[4];
    const float* w_out  = (const float*)d_in[5];
    float* out = (float*)d_out;

    float *proj, *y;
    __half *xh, *winh, *wouth, *ynh;
    cudaGetSymbolAddress((void**)&proj,  g_proj);
    cudaGetSymbolAddress((void**)&y,     g_y);
    cudaGetSymbolAddress((void**)&xh,    g_xh);
    cudaGetSymbolAddress((void**)&winh,  g_winh);
    cudaGetSymbolAddress((void**)&wouth, g_wouth);
    cudaGetSymbolAddress((void**)&ynh,   g_ynh);

    cudaFuncSetAttribute(fused_all,
                         cudaFuncAttributeMaxDynamicSharedMemorySize,
                         SMEM_DYN_BYTES);

    // 0. reset flags + merged fp32 -> fp16 conversion
    zero_flags_kernel<<<1, NMTILES>>>();
    convert_all_kernel<<<(CVT_TOTAL + 255) / 256, 256>>>(
        x, xh, w_in, winh, w_out, wouth);

    // 1. fully fused pipeline: proj GEMM -> scan(+conv) -> epilogue -> out GEMM
    fused_all<<<BLK_TOTAL, 256, SMEM_DYN_BYTES>>>(
        proj, conv_w, sw, y, xh, winh, norm_w, ynh, wouth, out);
}

// round 15
// speedup vs baseline: 1.4566x; 1.0213x over previous
#include <cuda_runtime.h>
#include <cuda_fp16.h>
#include <cuda_bf16.h>
#include <cstdint>

// ---------------------------------------------------------------------------
// Problem constants
// ---------------------------------------------------------------------------
#define BATCH   4
#define SEQ     4096
#define DMODEL  1024
#define NHEADS  8
#define HDIM    64
#define STATE   512            // NHEADS*HDIM
#define PROJW   2048           // 4*STATE
#define ROWS    (BATCH*SEQ)    // 16384

// GEMM tiling: block 128x256, 8 warps of 64x64, fp16 HMMA m16n8k16
#define BM 128
#define BN 256
#define NSTAGE 5
#define ROWB 48                         // padded smem row stride (bytes)
#define A_STAGE_B (BM * ROWB)           // 6144 B
#define B_STAGE_B (BN * ROWB)           // 12288 B
#define GEMM_SMEM_BYTES (NSTAGE * (A_STAGE_B + B_STAGE_B))   // 92160 B

#define NTILES_N 8                      // 2048 / BN
#define NMTILES  128                    // ROWS / BM

// Scan input staging: chunks of 64 steps, 3 operands (xi_raw | xf | xr)
#define CHUNK    64
#define NCHUNKS  (SEQ / CHUNK)          // 64
#define OP_STRIDE  (CHUNK * 64)         // 4096 floats per operand
#define BUF_STRIDE (3 * OP_STRIDE)      // 12288 floats per buffer
#define SCAN_SMEM_BYTES (2 * BUF_STRIDE * 4)   // 98304 B

#define SMEM_DYN_BYTES (SCAN_SMEM_BYTES > GEMM_SMEM_BYTES ? \
                        SCAN_SMEM_BYTES : GEMM_SMEM_BYTES)   // 98304

// Fused grid layout
#define BLK_SCAN0   0
#define BLK_GEMM1   32
#define BLK_EPI     (32 + NMTILES * NTILES_N)          // 1056
#define BLK_GEMM2   (BLK_EPI + NMTILES)                // 1184
#define BLK_TOTAL   (BLK_GEMM2 + NMTILES * 4)          // 1696

// Merged conversion sizes (groups of 8 floats)
#define CVT_N1 (ROWS * DMODEL / 8)      // x      : 2097152
#define CVT_N2 (PROJW * DMODEL / 8)     // w_in   : 262144
#define CVT_N3 (DMODEL * STATE / 8)     // w_out  : 65536
#define CVT_TOTAL (CVT_N1 + CVT_N2 + CVT_N3)

// ---------------------------------------------------------------------------
// Scratch (device globals -- no runtime allocation allowed)
// ---------------------------------------------------------------------------
__device__ float  g_proj[(size_t)ROWS * PROJW];   // [xi_raw | xf | xr | g]
__device__ float  g_y   [(size_t)ROWS * STATE];   // recurrence output
__device__ __half g_xh  [(size_t)ROWS * DMODEL];  // x (fp16)
__device__ __half g_winh[(size_t)PROJW * DMODEL]; // w_in (fp16; xf/xr rows *0.5)
__device__ __half g_wouth[(size_t)DMODEL * STATE];// w_out (fp16)
__device__ __half g_ynh [(size_t)ROWS * STATE];   // gated+normed (fp16)
// one flag buffer: [0,128) proj m-tile (8=done), [128,256) y (8=done),
//                  [256,384) ynh (1=done). Zeroed via cudaMemsetAsync.
__device__ int    g_flagbuf[3 * NMTILES];

// ---------------------------------------------------------------------------
// Helpers
// ---------------------------------------------------------------------------
__device__ __forceinline__ unsigned long long pk2(float lo, float hi) {
    unsigned long long r;
    asm("mov.b64 %0, {%1, %2};" : "=l"(r) : "f"(lo), "f"(hi));
    return r;
}
__device__ __forceinline__ void fma2(unsigned long long& d,
                                     unsigned long long a,
                                     unsigned long long b) {
    asm("fma.rn.f32x2 %0, %1, %2, %0;" : "+l"(d) : "l"(a), "l"(b));
}
__device__ __forceinline__ unsigned long long add2(unsigned long long a,
                                                   unsigned long long b) {
    unsigned long long d;
    asm("add.rn.f32x2 %0, %1, %2;" : "=l"(d) : "l"(a), "l"(b));
    return d;
}
__device__ __forceinline__ float hadd2(unsigned long long v) {
    float a, b;
    asm("mov.b64 {%0, %1}, %2;" : "=f"(a), "=f"(b) : "l"(v));
    return a + b;
}
__device__ __forceinline__ float fsigmoid(float x) {
    return __fdividef(1.0f, 1.0f + __expf(-x));
}
__device__ __forceinline__ float tanh_fast(float x) {
    float y;
    asm("tanh.approx.f32 %0, %1;" : "=f"(y) : "f"(x));
    return y;
}
__device__ __forceinline__ float sigmoid_fast(float x) {
    return fmaf(0.5f, tanh_fast(0.5f * x), 0.5f);
}
// argument already pre-halved (weights/x prescaled by 0.5)
__device__ __forceinline__ float sigmoid_pre(float half_arg) {
    return fmaf(0.5f, tanh_fast(half_arg), 0.5f);
}
__device__ __forceinline__ int ld_acq(const int* p) {
    int v;
    asm volatile("ld.global.acquire.gpu.b32 %0, [%1];" : "=r"(v) : "l"(p));
    return v;
}
__device__ __forceinline__ void wait_flag(const int* p, int target) {
    while (ld_acq(p) < target) { __nanosleep(128); }
}
__device__ __forceinline__ float4 ldcg4(const float* p) {
    float4 v;
    asm volatile("ld.global.cg.v4.f32 {%0,%1,%2,%3}, [%4];"
                 : "=f"(v.x), "=f"(v.y), "=f"(v.z), "=f"(v.w) : "l"(p));
    return v;
}

// ---------------------------------------------------------------------------
// GEMM primitives
// ---------------------------------------------------------------------------
__device__ __forceinline__ void mma_f16(float* c, const uint32_t* a,
                                        uint32_t b0, uint32_t b1) {
    asm volatile(
        "mma.sync.aligned.m16n8k16.row.col.f32.f16.f16.f32 "
        "{%0,%1,%2,%3}, {%4,%5,%6,%7}, {%8,%9}, {%0,%1,%2,%3};\n"
        : "+f"(c[0]), "+f"(c[1]), "+f"(c[2]), "+f"(c[3])
        : "r"(a[0]), "r"(a[1]), "r"(a[2]), "r"(a[3]), "r"(b0), "r"(b1));
}
__device__ __forceinline__ void ldsm4(uint32_t& r0, uint32_t& r1,
                                      uint32_t& r2, uint32_t& r3,
                                      uint32_t addr) {
    asm volatile("ldmatrix.sync.aligned.m8n8.x4.shared.b16 "
                 "{%0,%1,%2,%3}, [%4];"
                 : "=r"(r0), "=r"(r1), "=r"(r2), "=r"(r3) : "r"(addr));
}
__device__ __forceinline__ void cp16(uint32_t dst, const void* src) {
    asm volatile("cp.async.cg.shared.global [%0], [%1], 16;\n"
                 :: "r"(dst), "l"(src));
}

// ---------------------------------------------------------------------------
// Merged pre-pass: fp32 -> fp16 (rn). w_in rows [512,1536) (xf|xr) are
// prescaled by 0.5 (exact) so the scan's sigmoid needs no inner 0.5 mul.
// ---------------------------------------------------------------------------
__global__ void __launch_bounds__(256)
convert_all_kernel(const float* __restrict__ x, __half* __restrict__ xh,
                   const float* __restrict__ w_in, __half* __restrict__ winh,
                   const float* __restrict__ w_out, __half* __restrict__ wouth)
{
    int g = blockIdx.x * 256 + threadIdx.x;
    const float* src;
    __half* dst;
    float scale = 1.0f;
    if (g < CVT_N1) {
        src = x + (size_t)g * 8;            dst = xh + (size_t)g * 8;
    } else if (g < CVT_N1 + CVT_N2) {
        int h8 = g - CVT_N1;
        int row = h8 >> 7;                  // 128 groups of 8 per 1024-col row
        if (row >= 512 && row < 1536) scale = 0.5f;
        src = w_in + (size_t)h8 * 8;        dst = winh + (size_t)h8 * 8;
    } else if (g < CVT_TOTAL) {
        int h8 = g - CVT_N1 - CVT_N2;
        src = w_out + (size_t)h8 * 8;       dst = wouth + (size_t)h8 * 8;
    } else {
        return;
    }
    const float4* s = (const float4*)src;
    float4 a = s[0], b = s[1];
    __half2 h0 = __floats2half2_rn(a.x * scale, a.y * scale);
    __half2 h1 = __floats2half2_rn(a.z * scale, a.w * scale);
    __half2 h2 = __floats2half2_rn(b.x * scale, b.y * scale);
    __half2 h3 = __floats2half2_rn(b.z * scale, b.w * scale);
    uint4 o;
    o.x = *(uint32_t*)&h0; o.y = *(uint32_t*)&h1;
    o.z = *(uint32_t*)&h2; o.w = *(uint32_t*)&h3;
    *(uint4*)dst = o;
}

// ---------------------------------------------------------------------------
// 128x256 fp16 GEMM body (NT): C[m,n] = sum_k A[m,k]*B[n,k], fp32 accum/out.
// ---------------------------------------------------------------------------
__device__ __forceinline__ void gemm_body(const __half* __restrict__ Ag0,
                                          const __half* __restrict__ Bg0,
                                          float* __restrict__ Cg0,
                                          int K, int ldc)
{
    extern __shared__ char smem_dyn[];
    char* Asm = smem_dyn;
    char* Bsm = smem_dyn + NSTAGE * A_STAGE_B;
    const uint32_t aBase = (uint32_t)__cvta_generic_to_shared(Asm);
    const uint32_t bBase = (uint32_t)__cvta_generic_to_shared(Bsm);

    const int tid   = threadIdx.x;
    const int lane  = tid & 31;
    const int warp  = tid >> 5;
    const int group = lane >> 2;
    const int tig   = lane & 3;
    const int wm = (warp >> 2) * 64;
    const int wn = (warp & 3) * 64;

    const int lj = lane >> 3;
    const int lrr = lane & 7;
    const uint32_t fragOff =
        (uint32_t)(((lj & 1) * 8 + lrr) * ROWB + (lj >> 1) * 16);

    float c[4][8][4];
#pragma unroll
    for (int mt = 0; mt < 4; mt++)
#pragma unroll
        for (int nt = 0; nt < 8; nt++)
#pragma unroll
            for (int q = 0; q < 4; q++) c[mt][nt][q] = 0.0f;

    const int arow  = tid >> 1;
    const int ahalf = tid & 1;
    const uint32_t aOff  = (uint32_t)(arow * ROWB + ahalf * 16);
    const uint32_t bOff0 = aOff;
    const uint32_t bOff1 = (uint32_t)((arow + 128) * ROWB + ahalf * 16);
    const int niter = K >> 4;

    auto load_stage = [&](int st, int ko) {
        const uint32_t aS = aBase + (uint32_t)(st * A_STAGE_B);
        const uint32_t bS = bBase + (uint32_t)(st * B_STAGE_B);
        cp16(aS + aOff,  Ag0 + (size_t)arow * K + ko + ahalf * 8);
        cp16(bS + bOff0, Bg0 + (size_t)arow * K + ko + ahalf * 8);
        cp16(bS + bOff1, Bg0 + (size_t)(arow + 128) * K + ko + ahalf * 8);
        asm volatile("cp.async.commit_group;\n");
    };

    load_stage(0, 0);
    load_stage(1, 16);
    load_stage(2, 32);
    load_stage(3, 48);

    int st = 0, ldst = 4;
    for (int it = 0; it < niter; it++) {
        asm volatile("cp.async.wait_group 3;\n");
        __syncthreads();

        const uint32_t aT = aBase + (uint32_t)(st * A_STAGE_B);
        const uint32_t bT = bBase + (uint32_t)(st * B_STAGE_B);

        uint32_t a[4][4], bf[4][4];
#pragma unroll
        for (int mt = 0; mt < 4; mt++)
            ldsm4(a[mt][0], a[mt][1], a[mt][2], a[mt][3],
                  aT + (uint32_t)((wm + mt * 16) * ROWB) + fragOff);
#pragma unroll
        for (int bt = 0; bt < 4; bt++)
            ldsm4(bf[bt][0], bf[bt][1], bf[bt][2], bf[bt][3],
                  bT + (uint32_t)((wn + bt * 16) * ROWB) + fragOff);

#pragma unroll
        for (int mt = 0; mt < 4; mt++)
#pragma unroll
            for (int nt = 0; nt < 8; nt++) {
                const int bt = nt >> 1, s = nt & 1;
                mma_f16(c[mt][nt], a[mt], bf[bt][s], bf[bt][s + 2]);
            }

        if (it + 4 < niter)
            load_stage(ldst, (it + 4) * 16);
        else
            asm volatile("cp.async.commit_group;\n");

        st   = (st   + 1 == NSTAGE) ? 0 : st + 1;
        ldst = (ldst + 1 == NSTAGE) ? 0 : ldst + 1;
    }

#pragma unroll
    for (int mt = 0; mt < 4; mt++) {
        const int m0 = wm + mt * 16 + group;
#pragma unroll
        for (int nt = 0; nt < 8; nt++) {
            const int n0 = wn + nt * 8 + 2 * tig;
            *(float2*)(Cg0 + (size_t)m0 * ldc + n0) =
                make_float2(c[mt][nt][0], c[mt][nt][1]);
            *(float2*)(Cg0 + (size_t)(m0 + 8) * ldc + n0) =
                make_float2(c[mt][nt][2], c[mt][nt][3]);
        }
    }
}

// ---------------------------------------------------------------------------
// Sequential recurrence; smem-staged inputs; conv+silu on r-warps one step
// ahead. Gate weights prescaled 0.5; xg/xiv folded into accumulator init;
// f keeps its h[k] in a register; hn tail is one FMA after tanh.
// ---------------------------------------------------------------------------
__device__ void scan_body(const float* proj,
                          const float* __restrict__ cw,
                          const float* __restrict__ sw,
                          float* __restrict__ y, int bh, float* stage)
{
    const int tid  = threadIdx.x;
    const int k    = tid & 63;
    const bool isf = tid < 64;
    const int head = bh & 7;
    const int b    = bh >> 3;

    int* flags_proj = g_flagbuf;
    int* flags_y    = g_flagbuf + NMTILES;

    __shared__ __align__(16) float h_sh[64];
    __shared__ __align__(16) float hr_sh[64];
    __shared__ __align__(16) float xi_sh[2][64];   // conv+silu handoff

    unsigned long long wg[32];  // 0.5*Wf (f) or 0.5*Wr (r), column k
    unsigned long long wz[32];  // W  (f-threads only)
    {
        const int gidx = isf ? (NHEADS + head) : (2 * NHEADS + head);
        const float* base = sw + (size_t)gidx * 64 * 64 + k;
#pragma unroll
        for (int i = 0; i < 32; i++)
            wg[i] = pk2(0.5f * base[(2 * i) * 64],
                        0.5f * base[(2 * i + 1) * 64]);
        if (isf) {
            const float* bz = sw + (size_t)head * 64 * 64 + k;
#pragma unroll
            for (int i = 0; i < 32; i++)
                wz[i] = pk2(bz[(2 * i) * 64], bz[(2 * i + 1) * 64]);
        }
    }

    // conv weights + rolling window: r-threads only
    float cw0 = 0.f, cw1 = 0.f, cw2 = 0.f, cw3 = 0.f;
    if (!isf) {
        const float* cwp = cw + (size_t)(head * HDIM + k) * 4;
        cw0 = cwp[0]; cw1 = cwp[1]; cw2 = cwp[2]; cw3 = cwp[3];
    }
    float rm1 = 0.f, rm2 = 0.f, rm3 = 0.f;
    float h_reg = 0.f;                  // f's own h[k]

    if (tid < 64) h_sh[tid] = 0.0f;

    const size_t rowbase = (size_t)b * SEQ;

    const int trow = tid >> 4;      // 0..7
    const int tq4  = tid & 15;      // 0..15
    const uint32_t stBase = (uint32_t)__cvta_generic_to_shared(stage);

    auto stage_chunk = [&](int ch) {
        const int s0 = ch * CHUNK;
        const uint32_t dst0 = stBase
            + (uint32_t)((ch & 1) * BUF_STRIDE) * 4u;
        const float* src0 = proj + (rowbase + s0) * PROJW
                            + head * HDIM + tq4 * 4;
#pragma unroll
        for (int op = 0; op < 3; op++) {
            const int opoff = op * STATE;
#pragma unroll
            for (int i = 0; i < 8; i++) {
                const int row = i * 8 + trow;
                cp16(dst0 + (uint32_t)((op * OP_STRIDE + row * 64 + tq4 * 4) * 4),
                     src0 + (size_t)row * PROJW + opoff);
            }
        }
    };

    if (tid == 0) wait_flag(&flags_proj[b * 32 + 0], NTILES_N);
    __syncthreads();
    stage_chunk(0); asm volatile("cp.async.commit_group;\n");
    stage_chunk(1); asm volatile("cp.async.commit_group;\n");

    float* y_ptr = y + rowbase * STATE + head * HDIM + k;

    const ulonglong2* hp  = (const ulonglong2*)h_sh;
    const ulonglong2* hrp = (const ulonglong2*)hr_sh;

    for (int ch = 0; ch < NCHUNKS; ch++) {
        asm volatile("cp.async.wait_group 1;\n");
        __syncthreads();

        const float* bufp = stage + (ch & 1) * BUF_STRIDE;
        const float* xg_s = bufp + (isf ? OP_STRIDE : 2 * OP_STRIDE) + k;
        const float* xi_raw_s = bufp + k;     // op 0: raw xi
        const int sb = ch * CHUNK;

        // chunk top: r computes conv+silu for step 0
        if (!isf) {
            const float raw = xi_raw_s[0];
            const float a = fmaf(cw3, raw,
                             fmaf(cw2, rm1, fmaf(cw1, rm2, cw0 * rm3)));
            xi_sh[0][k] = a * sigmoid_fast(a);
            rm3 = rm2; rm2 = rm1; rm1 = raw;
        }

#pragma unroll 8
        for (int js = 0; js < CHUNK; js++) {
            const float xg = xg_s[js * 64];   // pre-halved (prescaled w_in)

            // phase A: gate dot over h; xg folded into accumulator init
            unsigned long long a0 = pk2(xg, 0.0f);
            unsigned long long a1 = 0ull, a2 = 0ull, a3 = 0ull;
#pragma unroll
            for (int i = 0; i < 8; i++) {
                ulonglong2 p0 = hp[2 * i];
                ulonglong2 p1 = hp[2 * i + 1];
                fma2(a0, p0.x, wg[4 * i + 0]);
                fma2(a1, p0.y, wg[4 * i + 1]);
                fma2(a2, p1.x, wg[4 * i + 2]);
                fma2(a3, p1.y, wg[4 * i + 3]);
            }
            const float gate =
                sigmoid_pre(hadd2(add2(add2(a0, a1), add2(a2, a3))));
            if (!isf) hr_sh[k] = h_sh[k] * gate;
            __syncthreads();                       // bar1: hr (+xi) visible

            float hn = 0.0f;
            if (isf) {
                // pre-compute the post-tanh algebra off the serial chain
                const float p = gate * h_reg;      // g*h
                const float q = 1.0f - gate;       // (1-g)
                const float xiv = xi_sh[js & 1][k];
                unsigned long long z0 = pk2(xiv, 0.0f);
                unsigned long long z1 = 0ull, z2 = 0ull, z3 = 0ull;
#pragma unroll
                for (int i = 0; i < 8; i++) {
                    ulonglong2 p0 = hrp[2 * i];
                    ulonglong2 p1 = hrp[2 * i + 1];
                    fma2(z0, p0.x, wz[4 * i + 0]);
                    fma2(z1, p0.y, wz[4 * i + 1]);
                    fma2(z2, p1.x, wz[4 * i + 2]);
                    fma2(z3, p1.y, wz[4 * i + 3]);
                }
                const float z =
                    tanh_fast(hadd2(add2(add2(z0, z1), add2(z2, z3))));
                hn = fmaf(q, z, p);                // g*h + (1-g)*z
                h_sh[k] = hn;
                h_reg = hn;
            } else if (js < CHUNK - 1) {
                // phase B (r): conv+silu for step js+1 into the other slot
                const float raw = xi_raw_s[(js + 1) * 64];
                const float a = fmaf(cw3, raw,
                                 fmaf(cw2, rm1, fmaf(cw1, rm2, cw0 * rm3)));
                xi_sh[(js + 1) & 1][k] = a * sigmoid_fast(a);
                rm3 = rm2; rm2 = rm1; rm1 = raw;
            }
            __syncthreads();                       // bar2: new h visible

            if (isf) y_ptr[(size_t)(sb + js) * STATE] = hn;  // off-path store
        }

        // publish y progress for the m-tile just completed (every 2 chunks)
        if (ch & 1) {
            __threadfence();
            __syncthreads();
            if (tid == 0) atomicAdd(&flags_y[b * 32 + (ch >> 1)], 1);
        }

        if (ch + 2 < NCHUNKS) {
            if (tid == 0) wait_flag(&flags_proj[b * 32 + ((ch + 2) >> 1)],
                                    NTILES_N);
            __syncthreads();
            stage_chunk(ch + 2);
        }
        asm volatile("cp.async.commit_group;\n");
    }
}

// ---------------------------------------------------------------------------
// Epilogue body: one m-tile (128 rows). Gated on y + g availability.
// ---------------------------------------------------------------------------
__device__ void epilogue_body(const float* y, const float* proj,
                              const float* __restrict__ norm_w,
                              __half* yn, int by)
{
    const int tid = threadIdx.x;
    if (tid == 0) {
        wait_flag(&g_flagbuf[by], NTILES_N);             // g cols ready
        wait_flag(&g_flagbuf[NMTILES + by], NHEADS);     // y rows ready
    }
    __syncthreads();

    const int w = tid >> 5, lane = tid & 31;
    float nw[16];
#pragma unroll
    for (int j = 0; j < 4; j++) {
        float4 t = *(const float4*)(norm_w + lane * 4 + j * 128);
        nw[4 * j + 0] = t.x; nw[4 * j + 1] = t.y;
        nw[4 * j + 2] = t.z; nw[4 * j + 3] = t.w;
    }

    for (int rr = 0; rr < 16; rr++) {
        const int row = by * BM + w * 16 + rr;
        const float* yr = y    + (size_t)row * STATE;
        const float* gr = proj + (size_t)row * PROJW + 3 * STATE;
        float v[16];
        float ss = 0.0f;
#pragma unroll
        for (int j = 0; j < 4; j++) {
            float4 yv = ldcg4(yr + lane * 4 + j * 128);
            float4 gv = ldcg4(gr + lane * 4 + j * 128);
            float v0 = yv.x * gv.x * fsigmoid(gv.x);
            float v1 = yv.y * gv.y * fsigmoid(gv.y);
            float v2 = yv.z * gv.z * fsigmoid(gv.z);
            float v3 = yv.w * gv.w * fsigmoid(gv.w);
            v[4 * j + 0] = v0; v[4 * j + 1] = v1;
            v[4 * j + 2] = v2; v[4 * j + 3] = v3;
            ss += v0 * v0 + v1 * v1 + v2 * v2 + v3 * v3;
        }
#pragma unroll
        for (int off = 16; off > 0; off >>= 1)
            ss += __shfl_xor_sync(0xffffffffu, ss, off);
        const float scale = rsqrtf(ss * (1.0f / 512.0f) + 1e-6f);
        __half* outr = yn + (size_t)row * STATE;
#pragma unroll
        for (int j = 0; j < 4; j++) {
            __half2 h0 = __floats2half2_rn(v[4 * j + 0] * scale * nw[4 * j + 0],
                                           v[4 * j + 1] * scale * nw[4 * j + 1]);
            __half2 h1 = __floats2half2_rn(v[4 * j + 2] * scale * nw[4 * j + 2],
                                           v[4 * j + 3] * scale * nw[4 * j + 3]);
            uint2 o;
            o.x = *(uint32_t*)&h0; o.y = *(uint32_t*)&h1;
            *(uint2*)(outr + lane * 4 + j * 128) = o;
        }
    }

    __threadfence();
    __syncthreads();
    if (tid == 0) atomicAdd(&g_flagbuf[2 * NMTILES + by], 1);
}

// ---------------------------------------------------------------------------
// Fused kernel (same DAG as R13/14): scan | proj GEMM | epilogue | out GEMM
// ---------------------------------------------------------------------------
__global__ void __launch_bounds__(256)
fused_all(float* proj,
          const float* __restrict__ cw,
          const float* __restrict__ sw,
          float* __restrict__ y,
          const __half* __restrict__ xh,
          const __half* __restrict__ winh,
          const float* __restrict__ norm_w,
          __half* ynh,
          const __half* __restrict__ wouth,
          float* __restrict__ out)
{
    extern __shared__ char smem_dyn[];
    const int bx = blockIdx.x;
    if (bx < BLK_GEMM1) {
        if (threadIdx.x >= 128) return;
        scan_body(proj, cw, sw, y, bx, (float*)smem_dyn);
    } else if (bx < BLK_EPI) {
        const int idx = bx - BLK_GEMM1;
        const int nt = idx & 7;
        const int m_order = idx >> 3;
        const int by = (m_order & 3) * 32 + (m_order >> 2);
        gemm_body(xh + (size_t)by * BM * DMODEL,
                  winh + (size_t)nt * BN * DMODEL,
                  proj + (size_t)by * BM * PROJW + nt * BN,
                  DMODEL, PROJW);
        __threadfence();
        __syncthreads();
        if (threadIdx.x == 0) atomicAdd(&g_flagbuf[by], 1);
    } else if (bx < BLK_GEMM2) {
        const int m_order = bx - BLK_EPI;
        const int by = (m_order & 3) * 32 + (m_order >> 2);
        epilogue_body(y, proj, norm_w, ynh, by);
    } else {
        const int idx = bx - BLK_GEMM2;
        const int nt = idx & 3;
        const int m_order = idx >> 2;
        const int by = (m_order & 3) * 32 + (m_order >> 2);
        if (threadIdx.x == 0) wait_flag(&g_flagbuf[2 * NMTILES + by], 1);
        __syncthreads();
        gemm_body(ynh + (size_t)by * BM * STATE,
                  wouth + (size_t)nt * BN * STATE,
                  out + (size_t)by * BM * DMODEL + nt * BN,
                  STATE, DMODEL);
    }
}

// ---------------------------------------------------------------------------
// Launch
// ---------------------------------------------------------------------------
extern "C" void kernel_launch(void* const* d_in, const int* in_sizes, int n_in,
                              void* d_out, int out_size)
{
    const float* x      = (const float*)d_in[0];
    const float* w_in   = (const float*)d_in[1];
    const float* conv_w = (const float*)d_in[2];
    const float* sw     = (const float*)d_in[3];
    const float* norm_w = (const float*)d_in[4];
    const float* w_out  = (const float*)d_in[5];
    float* out = (float*)d_out;

    float *proj, *y;
    __half *xh, *winh, *wouth, *ynh;
    int* flagbuf;
    cudaGetSymbolAddress((void**)&proj,    g_proj);
    cudaGetSymbolAddress((void**)&y,       g_y);
    cudaGetSymbolAddress((void**)&xh,      g_xh);
    cudaGetSymbolAddress((void**)&winh,    g_winh);
    cudaGetSymbolAddress((void**)&wouth,   g_wouth);
    cudaGetSymbolAddress((void**)&ynh,     g_ynh);
    cudaGetSymbolAddress((void**)&flagbuf, g_flagbuf);

    cudaFuncSetAttribute(fused_all,
                         cudaFuncAttributeMaxDynamicSharedMemorySize,
                         SMEM_DYN_BYTES);

    // 0. zero flags (async memset; graph-capturable) + merged conversion
    cudaMemsetAsync(flagbuf, 0, 3 * NMTILES * sizeof(int));
    convert_all_kernel<<<(CVT_TOTAL + 255) / 256, 256>>>(
        x, xh, w_in, winh, w_out, wouth);

    // 1. fully fused pipeline: proj GEMM -> scan(+conv) -> epilogue -> out GEMM
    fused_all<<<BLK_TOTAL, 256, SMEM_DYN_BYTES>>>(
        proj, conv_w, sw, y, xh, winh, norm_w, ynh, wouth, out);
}